// round 4
// baseline (speedup 1.0000x reference)
#include <cuda_runtime.h>
#include <cuda_bf16.h>
#include <cstdint>

// Problem constants (fixed by the reference setup)
#define NN     100000
#define EE     3200000
#define ETEST  500000
#define FIN    256
#define FH     16
#define FOUT   64

// ---------------- device scratch (no allocs allowed) ----------------
__device__ __align__(256) int   g_deg[NN];
__device__ __align__(256) float g_dinv[NN];
__device__ __align__(256) float g_hs [NN * FH];   // (x@W1) * dinv[row]
__device__ __align__(256) float g_agg[NN * FH];   // scatter accumulator (reused both layers)
__device__ __align__(256) float g_zs [NN * FH];   // relu(z1) * dinv[row]
__device__ __align__(256) float g_a2 [NN * FH];   // layer-2 aggregated features (16-dim)
__device__ __align__(256) float g_q  [NN * FH];   // q = G @ a2
__device__ __align__(256) float g_p  [NN];        // p = a2 . u + c/2
__device__ __align__(256) float g_G  [FH * FH];   // W2 W2^T
__device__ __align__(256) float g_u  [FH];        // W2 b2
__device__ float g_c;                             // ||b2||^2

// ---------------- kernels ----------------

// zero deg + agg accumulator
__global__ void k_zero() {
    int t = blockIdx.x * blockDim.x + threadIdx.x;
    if (t < (NN * FH) / 4) {
        ((float4*)g_agg)[t] = make_float4(0.f, 0.f, 0.f, 0.f);
    }
    if (t < NN) g_deg[t] = 0;
}

// G = W2 W2^T, u = W2 b2, c = ||b2||^2   (W2 is (16,64) row-major)
__global__ void k_guc(const float* __restrict__ W2, const float* __restrict__ b2) {
    int t = threadIdx.x;
    if (t < FH * FH) {
        int i = t >> 4, j = t & 15;
        float s = 0.f;
        #pragma unroll
        for (int k = 0; k < FOUT; k++) s += W2[i * FOUT + k] * W2[j * FOUT + k];
        g_G[t] = s;
        if (t < FH) {
            float su = 0.f;
            #pragma unroll
            for (int k = 0; k < FOUT; k++) su += W2[t * FOUT + k] * b2[k];
            g_u[t] = su;
        }
        if (t == 0) {
            float sc = 0.f;
            #pragma unroll
            for (int k = 0; k < FOUT; k++) sc += b2[k] * b2[k];
            g_c = sc;
        }
    }
}

// in-degree over dst (self-loop handled analytically as +1)
__global__ void k_deg(const int* __restrict__ dst) {
    int e = blockIdx.x * blockDim.x + threadIdx.x;
    if (e < EE) atomicAdd(&g_deg[dst[e]], 1);
}

__global__ void k_dinv() {
    int i = blockIdx.x * blockDim.x + threadIdx.x;
    if (i < NN) g_dinv[i] = rsqrtf((float)g_deg[i] + 1.0f);
}

// hs = (x @ W1) * dinv[row].   One warp computes 4 rows; W1 staged in smem
// with pad-17 layout so the (k = lane + 32t) access pattern is conflict-free.
__global__ void k_gemm1(const float* __restrict__ x, const float* __restrict__ W1) {
    __shared__ float w[FIN * 17];
    int tid = threadIdx.x;
    for (int i = tid; i < FIN * FH; i += blockDim.x) {
        int k = i >> 4, j = i & 15;
        w[k * 17 + j] = W1[i];
    }
    __syncthreads();

    int warp = tid >> 5, lane = tid & 31;
    int row0 = (blockIdx.x * (blockDim.x >> 5) + warp) * 4;
    if (row0 >= NN) return;

    float acc[4][16];
    #pragma unroll
    for (int r = 0; r < 4; r++)
        #pragma unroll
        for (int j = 0; j < 16; j++) acc[r][j] = 0.f;

    const float* x0 = x + (size_t)row0 * FIN;
    #pragma unroll
    for (int t = 0; t < 8; t++) {
        int k = lane + 32 * t;
        float xv0 = x0[k];
        float xv1 = x0[FIN + k];
        float xv2 = x0[2 * FIN + k];
        float xv3 = x0[3 * FIN + k];
        #pragma unroll
        for (int j = 0; j < 16; j++) {
            float wv = w[k * 17 + j];
            acc[0][j] += xv0 * wv;
            acc[1][j] += xv1 * wv;
            acc[2][j] += xv2 * wv;
            acc[3][j] += xv3 * wv;
        }
    }
    // butterfly-reduce each output across the warp
    #pragma unroll
    for (int r = 0; r < 4; r++)
        #pragma unroll
        for (int j = 0; j < 16; j++) {
            float v = acc[r][j];
            v += __shfl_xor_sync(0xffffffffu, v, 16);
            v += __shfl_xor_sync(0xffffffffu, v, 8);
            v += __shfl_xor_sync(0xffffffffu, v, 4);
            v += __shfl_xor_sync(0xffffffffu, v, 2);
            v += __shfl_xor_sync(0xffffffffu, v, 1);
            acc[r][j] = v;
        }
    if (lane < 16) {
        #pragma unroll
        for (int r = 0; r < 4; r++) {
            int row = row0 + r;
            float o = 0.f;
            #pragma unroll
            for (int j = 0; j < 16; j++)
                if (lane == j) o = acc[r][j];
            g_hs[row * FH + lane] = o * g_dinv[row];
        }
    }
}

// Layer-1 edge scatter: g_agg[dst] += g_hs[src]  (globals referenced in
// DEVICE code — never passed from host; host-side device-symbol args were
// the R2/R3 silent-failure bug on GB300 ATS)
__global__ void k_agg1(const int* __restrict__ src, const int* __restrict__ dst) {
    int e = blockIdx.x * blockDim.x + threadIdx.x;
    if (e >= EE) return;
    int s = src[e], d = dst[e];
    const float4* h = (const float4*)(g_hs + (size_t)s * FH);
    float4 v0 = h[0], v1 = h[1], v2 = h[2], v3 = h[3];
    float* o = g_agg + (size_t)d * FH;
    atomicAdd(o + 0,  v0.x); atomicAdd(o + 1,  v0.y);
    atomicAdd(o + 2,  v0.z); atomicAdd(o + 3,  v0.w);
    atomicAdd(o + 4,  v1.x); atomicAdd(o + 5,  v1.y);
    atomicAdd(o + 6,  v1.z); atomicAdd(o + 7,  v1.w);
    atomicAdd(o + 8,  v2.x); atomicAdd(o + 9,  v2.y);
    atomicAdd(o + 10, v2.z); atomicAdd(o + 11, v2.w);
    atomicAdd(o + 12, v3.x); atomicAdd(o + 13, v3.y);
    atomicAdd(o + 14, v3.z); atomicAdd(o + 15, v3.w);
}

// Layer-2 edge scatter: g_agg[dst] += g_zs[src]
__global__ void k_agg2(const int* __restrict__ src, const int* __restrict__ dst) {
    int e = blockIdx.x * blockDim.x + threadIdx.x;
    if (e >= EE) return;
    int s = src[e], d = dst[e];
    const float4* h = (const float4*)(g_zs + (size_t)s * FH);
    float4 v0 = h[0], v1 = h[1], v2 = h[2], v3 = h[3];
    float* o = g_agg + (size_t)d * FH;
    atomicAdd(o + 0,  v0.x); atomicAdd(o + 1,  v0.y);
    atomicAdd(o + 2,  v0.z); atomicAdd(o + 3,  v0.w);
    atomicAdd(o + 4,  v1.x); atomicAdd(o + 5,  v1.y);
    atomicAdd(o + 6,  v1.z); atomicAdd(o + 7,  v1.w);
    atomicAdd(o + 8,  v2.x); atomicAdd(o + 9,  v2.y);
    atomicAdd(o + 10, v2.z); atomicAdd(o + 11, v2.w);
    atomicAdd(o + 12, v3.x); atomicAdd(o + 13, v3.y);
    atomicAdd(o + 14, v3.z); atomicAdd(o + 15, v3.w);
}

// z1 = relu(dinv*(agg + hs) + b1);  zs = z1*dinv;  re-zero agg for layer 2
__global__ void k_z1(const float* __restrict__ b1) {
    int t = blockIdx.x * blockDim.x + threadIdx.x;   // one thread = 4 features
    if (t >= NN * 4) return;
    int i = t >> 2;
    float di = g_dinv[i];
    float4 a  = ((float4*)g_agg)[t];
    float4 h  = ((float4*)g_hs)[t];
    float4 bb = ((const float4*)b1)[t & 3];
    float4 z;
    z.x = fmaxf(di * (a.x + h.x) + bb.x, 0.f) * di;
    z.y = fmaxf(di * (a.y + h.y) + bb.y, 0.f) * di;
    z.z = fmaxf(di * (a.z + h.z) + bb.z, 0.f) * di;
    z.w = fmaxf(di * (a.w + h.w) + bb.w, 0.f) * di;
    ((float4*)g_zs)[t] = z;
    ((float4*)g_agg)[t] = make_float4(0.f, 0.f, 0.f, 0.f);
}

// a2 = dinv*(agg + zs);  q = G a2;  p = a2.u + c/2
__global__ void k_a2() {
    __shared__ float Gs[FH * FH];
    __shared__ float us[FH];
    __shared__ float cs;
    int tid = threadIdx.x;
    if (tid < FH * FH) Gs[tid] = g_G[tid];
    if (tid < FH) us[tid] = g_u[tid];
    if (tid == 0) cs = g_c;
    __syncthreads();

    int i = blockIdx.x * blockDim.x + tid;
    if (i >= NN) return;
    float di = g_dinv[i];
    float a[16];
    const float4* ag = (const float4*)(g_agg + i * FH);
    const float4* zz = (const float4*)(g_zs + i * FH);
    #pragma unroll
    for (int v = 0; v < 4; v++) {
        float4 av = ag[v], zv = zz[v];
        a[v * 4 + 0] = di * (av.x + zv.x);
        a[v * 4 + 1] = di * (av.y + zv.y);
        a[v * 4 + 2] = di * (av.z + zv.z);
        a[v * 4 + 3] = di * (av.w + zv.w);
    }
    float p = 0.5f * cs;
    float4* qo = (float4*)(g_q + i * FH);
    float4* ao = (float4*)(g_a2 + i * FH);
    #pragma unroll
    for (int v = 0; v < 4; v++) {
        float4 qv;
        float* qf = (float*)&qv;
        #pragma unroll
        for (int jj = 0; jj < 4; jj++) {
            int j = v * 4 + jj;
            float s = 0.f;
            #pragma unroll
            for (int k = 0; k < 16; k++) s += Gs[j * FH + k] * a[k];
            qf[jj] = s;
            p += a[j] * us[j];
        }
        qo[v] = qv;
        ao[v] = make_float4(a[v * 4], a[v * 4 + 1], a[v * 4 + 2], a[v * 4 + 3]);
    }
    g_p[i] = p;
}

// logits[e] = q[s] . a2[d] + p[s] + p[d]
__global__ void k_logits(const int* __restrict__ pos, const int* __restrict__ neg,
                         float* __restrict__ out) {
    int e = blockIdx.x * blockDim.x + threadIdx.x;
    if (e >= 2 * ETEST) return;
    int s, d;
    if (e < ETEST) { s = pos[e];         d = pos[ETEST + e]; }
    else           { s = neg[e - ETEST]; d = neg[ETEST + (e - ETEST)]; }
    const float4* qs = (const float4*)(g_q  + (size_t)s * FH);
    const float4* ad = (const float4*)(g_a2 + (size_t)d * FH);
    float acc = g_p[s] + g_p[d];
    #pragma unroll
    for (int v = 0; v < 4; v++) {
        float4 qv = qs[v], av = ad[v];
        acc += qv.x * av.x + qv.y * av.y + qv.z * av.z + qv.w * av.w;
    }
    out[e] = acc;
}

// ---------------- launch ----------------
extern "C" void kernel_launch(void* const* d_in, const int* in_sizes, int n_in,
                              void* d_out, int out_size) {
    // Resolve inputs BY SIZE (robust to metadata ordering).
    const float* x  = nullptr; const int* tei = nullptr;
    const int*   pos = nullptr; const int* neg = nullptr;
    const float* W1 = nullptr; const float* b1 = nullptr;
    const float* W2 = nullptr; const float* b2 = nullptr;
    for (int i = 0; i < n_in; i++) {
        int sz = in_sizes[i];
        const void* p = d_in[i];
        if      (sz == NN * FIN)   x   = (const float*)p;
        else if (sz == 2 * EE)     tei = (const int*)p;
        else if (sz == 2 * ETEST) { if (!pos) pos = (const int*)p; else neg = (const int*)p; }
        else if (sz == FIN * FH)   W1  = (const float*)p;
        else if (sz == FH)         b1  = (const float*)p;
        else if (sz == FH * FOUT)  W2  = (const float*)p;
        else if (sz == FOUT)       b2  = (const float*)p;
    }
    float* out = (float*)d_out;

    const int* src = tei;
    const int* dst = tei + EE;

    k_zero  <<<(NN * 4 + 255) / 256, 256>>>();
    k_guc   <<<1, 256>>>(W2, b2);
    k_deg   <<<(EE + 255) / 256, 256>>>(dst);
    k_dinv  <<<(NN + 255) / 256, 256>>>();
    k_gemm1 <<<(NN / 4 + 7) / 8, 256>>>(x, W1);               // 8 warps/block, 4 rows/warp
    k_agg1  <<<(EE + 255) / 256, 256>>>(src, dst);
    k_z1    <<<(NN * 4 + 255) / 256, 256>>>(b1);
    k_agg2  <<<(EE + 255) / 256, 256>>>(src, dst);
    k_a2    <<<(NN + 255) / 256, 256>>>();
    k_logits<<<(2 * ETEST + 255) / 256, 256>>>(pos, neg, out);
}

// round 5
// speedup vs baseline: 2.2663x; 2.2663x over previous
#include <cuda_runtime.h>
#include <cuda_bf16.h>
#include <cstdint>

// Problem constants (fixed by the reference setup)
#define NN     100000
#define EE     3200000
#define ETEST  500000
#define FIN    256
#define FH     16
#define FOUT   64
#define NB     196        // scan blocks: ceil(NN/512)

// ---------------- device scratch (no allocs allowed) ----------------
__device__ __align__(256) int   g_deg   [NN];
__device__ __align__(256) int   g_cursor[NN];
__device__ __align__(256) int   g_rowptr[NN + 1];
__device__ __align__(256) int   g_bsum  [NB];
__device__ __align__(256) int   g_boff  [NB];
__device__ __align__(256) int   g_csr   [EE];
__device__ __align__(256) float g_dinv[NN];
__device__ __align__(256) float g_hs [NN * FH];   // (x@W1) * dinv[row]
__device__ __align__(256) float g_zs [NN * FH];   // relu(z1) * dinv[row]
__device__ __align__(256) float g_a2 [NN * FH];   // layer-2 node features (16-dim)
__device__ __align__(256) float g_q  [NN * FH];   // q = G @ a2
__device__ __align__(256) float g_p  [NN];        // p = a2 . u + c/2
__device__ __align__(256) float g_G  [FH * FH];   // W2 W2^T
__device__ __align__(256) float g_u  [FH];        // W2 b2
__device__ float g_c;                             // ||b2||^2

// ---------------- kernels ----------------

// zero deg + cursor
__global__ void k_zero() {
    int t = blockIdx.x * blockDim.x + threadIdx.x;
    if (t < NN) { g_deg[t] = 0; g_cursor[t] = 0; }
}

// G = W2 W2^T, u = W2 b2, c = ||b2||^2   (W2 is (16,64) row-major)
__global__ void k_guc(const float* __restrict__ W2, const float* __restrict__ b2) {
    int t = threadIdx.x;
    if (t < FH * FH) {
        int i = t >> 4, j = t & 15;
        float s = 0.f;
        #pragma unroll
        for (int k = 0; k < FOUT; k++) s += W2[i * FOUT + k] * W2[j * FOUT + k];
        g_G[t] = s;
        if (t < FH) {
            float su = 0.f;
            #pragma unroll
            for (int k = 0; k < FOUT; k++) su += W2[t * FOUT + k] * b2[k];
            g_u[t] = su;
        }
        if (t == 0) {
            float sc = 0.f;
            #pragma unroll
            for (int k = 0; k < FOUT; k++) sc += b2[k] * b2[k];
            g_c = sc;
        }
    }
}

// in-degree over dst (self-loop handled analytically as +1)
__global__ void k_deg(const int* __restrict__ dst) {
    int e = blockIdx.x * blockDim.x + threadIdx.x;
    if (e < EE) atomicAdd(&g_deg[dst[e]], 1);
}

// ---- 3-step exclusive prefix scan of g_deg into g_rowptr ----
__global__ void k_scan1() {
    __shared__ int sh[512];
    int tid = threadIdx.x;
    int i = blockIdx.x * 512 + tid;
    int v = (i < NN) ? g_deg[i] : 0;
    sh[tid] = v;
    __syncthreads();
    #pragma unroll
    for (int off = 1; off < 512; off <<= 1) {
        int t = (tid >= off) ? sh[tid - off] : 0;
        __syncthreads();
        sh[tid] += t;
        __syncthreads();
    }
    if (i < NN) g_rowptr[i] = sh[tid] - v;       // exclusive within block
    if (tid == 511) g_bsum[blockIdx.x] = sh[511];
}

__global__ void k_scan2() {
    __shared__ int sh[256];
    int tid = threadIdx.x;
    int v = (tid < NB) ? g_bsum[tid] : 0;
    sh[tid] = v;
    __syncthreads();
    #pragma unroll
    for (int off = 1; off < 256; off <<= 1) {
        int t = (tid >= off) ? sh[tid - off] : 0;
        __syncthreads();
        sh[tid] += t;
        __syncthreads();
    }
    if (tid < NB) g_boff[tid] = sh[tid] - v;     // exclusive block offsets
}

// add block offsets; also compute dinv here (fused)
__global__ void k_scan3() {
    int i = blockIdx.x * blockDim.x + threadIdx.x;
    if (i < NN) {
        g_rowptr[i] += g_boff[i >> 9];
        g_dinv[i] = rsqrtf((float)g_deg[i] + 1.0f);
    }
    if (i == 0) g_rowptr[NN] = EE;
}

// CSR fill: csr[rowptr[d] + pos] = src   (int atomics only, done once)
__global__ void k_fill(const int* __restrict__ src, const int* __restrict__ dst) {
    int e = blockIdx.x * blockDim.x + threadIdx.x;
    if (e >= EE) return;
    int d = dst[e];
    int pos = atomicAdd(&g_cursor[d], 1);
    g_csr[g_rowptr[d] + pos] = src[e];
}

// hs = (x @ W1) * dinv[row].   One warp computes 4 rows; W1 staged in smem
// with pad-17 layout so the (k = lane + 32t) access pattern is conflict-free.
__global__ void k_gemm1(const float* __restrict__ x, const float* __restrict__ W1) {
    __shared__ float w[FIN * 17];
    int tid = threadIdx.x;
    for (int i = tid; i < FIN * FH; i += blockDim.x) {
        int k = i >> 4, j = i & 15;
        w[k * 17 + j] = W1[i];
    }
    __syncthreads();

    int warp = tid >> 5, lane = tid & 31;
    int row0 = (blockIdx.x * (blockDim.x >> 5) + warp) * 4;
    if (row0 >= NN) return;

    float acc[4][16];
    #pragma unroll
    for (int r = 0; r < 4; r++)
        #pragma unroll
        for (int j = 0; j < 16; j++) acc[r][j] = 0.f;

    const float* x0 = x + (size_t)row0 * FIN;
    #pragma unroll
    for (int t = 0; t < 8; t++) {
        int k = lane + 32 * t;
        float xv0 = x0[k];
        float xv1 = x0[FIN + k];
        float xv2 = x0[2 * FIN + k];
        float xv3 = x0[3 * FIN + k];
        #pragma unroll
        for (int j = 0; j < 16; j++) {
            float wv = w[k * 17 + j];
            acc[0][j] += xv0 * wv;
            acc[1][j] += xv1 * wv;
            acc[2][j] += xv2 * wv;
            acc[3][j] += xv3 * wv;
        }
    }
    #pragma unroll
    for (int r = 0; r < 4; r++)
        #pragma unroll
        for (int j = 0; j < 16; j++) {
            float v = acc[r][j];
            v += __shfl_xor_sync(0xffffffffu, v, 16);
            v += __shfl_xor_sync(0xffffffffu, v, 8);
            v += __shfl_xor_sync(0xffffffffu, v, 4);
            v += __shfl_xor_sync(0xffffffffu, v, 2);
            v += __shfl_xor_sync(0xffffffffu, v, 1);
            acc[r][j] = v;
        }
    if (lane < 16) {
        #pragma unroll
        for (int r = 0; r < 4; r++) {
            int row = row0 + r;
            float o = 0.f;
            #pragma unroll
            for (int j = 0; j < 16; j++)
                if (lane == j) o = acc[r][j];
            g_hs[row * FH + lane] = o * g_dinv[row];
        }
    }
}

// Layer-1 pull gather + epilogue fused.
// One warp per node: lane = (neighbor parity)*16 + feature j.
// zs = relu(dinv*(sum_neighbors hs + hs[self]) + b1) * dinv
__global__ void k_gather1(const float* __restrict__ b1) {
    int warp = (blockIdx.x * blockDim.x + threadIdx.x) >> 5;
    int lane = threadIdx.x & 31;
    if (warp >= NN) return;
    int d = warp;
    int beg = g_rowptr[d], end = g_rowptr[d + 1];
    int j = lane & 15;
    int half = lane >> 4;

    float acc = 0.f;
    #pragma unroll 2
    for (int k = beg + half; k < end; k += 2) {
        int s = g_csr[k];
        acc += g_hs[s * FH + j];
    }
    acc += __shfl_xor_sync(0xffffffffu, acc, 16);

    if (lane < 16) {
        float di = g_dinv[d];
        float z = fmaxf(di * (acc + g_hs[d * FH + j]) + b1[j], 0.f);
        g_zs[d * FH + j] = z * di;
    }
}

// Layer-2 pull gather + full epilogue fused:
// a2 = dinv*(sum zs + zs[self]);  q = G a2;  p = a2.u + c/2
__global__ void k_gather2() {
    __shared__ float Gs[FH * FH];
    __shared__ float us[FH];
    __shared__ float cs;
    int tid = threadIdx.x;
    if (tid < FH * FH) Gs[tid] = g_G[tid];
    if (tid < FH) us[tid] = g_u[tid];
    if (tid == 0) cs = g_c;
    __syncthreads();

    int warp = (blockIdx.x * blockDim.x + tid) >> 5;
    int lane = tid & 31;
    if (warp >= NN) return;
    int d = warp;
    int beg = g_rowptr[d], end = g_rowptr[d + 1];
    int j = lane & 15;
    int half = lane >> 4;

    float acc = 0.f;
    #pragma unroll 2
    for (int k = beg + half; k < end; k += 2) {
        int s = g_csr[k];
        acc += g_zs[s * FH + j];
    }
    acc += __shfl_xor_sync(0xffffffffu, acc, 16);   // both halves now hold full sum

    float di = g_dinv[d];
    float a = di * (acc + g_zs[d * FH + j]);        // a2[j] (valid on all lanes)

    // q[j] = sum_k G[j][k] * a[k]  via lane broadcast
    float q = 0.f;
    #pragma unroll
    for (int k = 0; k < FH; k++) {
        float ak = __shfl_sync(0xffffffffu, a, k);
        q += Gs[j * FH + k] * ak;
    }
    // p = sum_j a[j]*u[j] + c/2  (reduce within low half)
    float pv = a * us[j];
    pv += __shfl_xor_sync(0xffffffffu, pv, 8);
    pv += __shfl_xor_sync(0xffffffffu, pv, 4);
    pv += __shfl_xor_sync(0xffffffffu, pv, 2);
    pv += __shfl_xor_sync(0xffffffffu, pv, 1);

    if (lane < 16) {
        g_a2[d * FH + j] = a;
        g_q [d * FH + j] = q;
        if (lane == 0) g_p[d] = pv + 0.5f * cs;
    }
}

// logits[e] = q[s] . a2[d] + p[s] + p[d]
__global__ void k_logits(const int* __restrict__ pos, const int* __restrict__ neg,
                         float* __restrict__ out) {
    int e = blockIdx.x * blockDim.x + threadIdx.x;
    if (e >= 2 * ETEST) return;
    int s, d;
    if (e < ETEST) { s = pos[e];         d = pos[ETEST + e]; }
    else           { s = neg[e - ETEST]; d = neg[ETEST + (e - ETEST)]; }
    const float4* qs = (const float4*)(g_q  + (size_t)s * FH);
    const float4* ad = (const float4*)(g_a2 + (size_t)d * FH);
    float acc = g_p[s] + g_p[d];
    #pragma unroll
    for (int v = 0; v < 4; v++) {
        float4 qv = qs[v], av = ad[v];
        acc += qv.x * av.x + qv.y * av.y + qv.z * av.z + qv.w * av.w;
    }
    out[e] = acc;
}

// ---------------- launch ----------------
extern "C" void kernel_launch(void* const* d_in, const int* in_sizes, int n_in,
                              void* d_out, int out_size) {
    // Resolve inputs BY SIZE (robust to metadata ordering).
    const float* x  = nullptr; const int* tei = nullptr;
    const int*   pos = nullptr; const int* neg = nullptr;
    const float* W1 = nullptr; const float* b1 = nullptr;
    const float* W2 = nullptr; const float* b2 = nullptr;
    for (int i = 0; i < n_in; i++) {
        int sz = in_sizes[i];
        const void* p = d_in[i];
        if      (sz == NN * FIN)   x   = (const float*)p;
        else if (sz == 2 * EE)     tei = (const int*)p;
        else if (sz == 2 * ETEST) { if (!pos) pos = (const int*)p; else neg = (const int*)p; }
        else if (sz == FIN * FH)   W1  = (const float*)p;
        else if (sz == FH)         b1  = (const float*)p;
        else if (sz == FH * FOUT)  W2  = (const float*)p;
        else if (sz == FOUT)       b2  = (const float*)p;
    }
    float* out = (float*)d_out;

    const int* src = tei;
    const int* dst = tei + EE;

    k_zero   <<<(NN + 255) / 256, 256>>>();
    k_guc    <<<1, 256>>>(W2, b2);
    k_deg    <<<(EE + 255) / 256, 256>>>(dst);
    k_scan1  <<<NB, 512>>>();
    k_scan2  <<<1, 256>>>();
    k_scan3  <<<(NN + 255) / 256, 256>>>();
    k_fill   <<<(EE + 255) / 256, 256>>>(src, dst);
    k_gemm1  <<<(NN / 4 + 7) / 8, 256>>>(x, W1);          // 8 warps/block, 4 rows/warp
    k_gather1<<<(NN * 32 + 255) / 256, 256>>>(b1);        // 1 warp / node
    k_gather2<<<(NN * 32 + 255) / 256, 256>>>();
    k_logits <<<(2 * ETEST + 255) / 256, 256>>>(pos, neg, out);
}

// round 9
// speedup vs baseline: 2.4082x; 1.0626x over previous
#include <cuda_runtime.h>
#include <cuda_bf16.h>
#include <cstdint>

// Problem constants (fixed by the reference setup)
#define NN     100000
#define EE     3200000
#define ETEST  500000
#define FIN    256
#define FH     16
#define FOUT   64
#define NB     196        // scan blocks: ceil(NN/512)

// ---------------- device scratch (no allocs allowed) ----------------
__device__ __align__(256) int   g_deg   [NN];
__device__ __align__(256) int   g_cursor[NN];
__device__ __align__(256) int   g_rowptr[NN + 1];
__device__ __align__(256) int   g_bsum  [NB];
__device__ __align__(256) int   g_boff  [NB];
__device__ __align__(256) int   g_csr   [EE];
__device__ __align__(256) float g_dinv[NN];
__device__ __align__(256) float g_hs [NN * FH];   // (x@W1) * dinv[row]
__device__ __align__(256) float g_zs [NN * FH];   // relu(z1) * dinv[row]
__device__ __align__(256) float g_a2 [NN * FH];   // layer-2 node features (16-dim)
__device__ __align__(256) float g_q  [NN * FH];   // q = G @ a2
__device__ __align__(256) float g_p  [NN];        // p = a2 . u + c/2
__device__ __align__(256) float g_G  [FH * FH];   // W2 W2^T
__device__ __align__(256) float g_u  [FH];        // W2 b2
__device__ float g_c;                             // ||b2||^2

// ---------------- kernels ----------------

// zero deg + cursor
__global__ void k_zero() {
    int t = blockIdx.x * blockDim.x + threadIdx.x;
    if (t < NN) { g_deg[t] = 0; g_cursor[t] = 0; }
}

// G = W2 W2^T, u = W2 b2, c = ||b2||^2   (W2 is (16,64) row-major)
__global__ void k_guc(const float* __restrict__ W2, const float* __restrict__ b2) {
    int t = threadIdx.x;
    if (t < FH * FH) {
        int i = t >> 4, j = t & 15;
        float s = 0.f;
        #pragma unroll
        for (int k = 0; k < FOUT; k++) s += W2[i * FOUT + k] * W2[j * FOUT + k];
        g_G[t] = s;
        if (t < FH) {
            float su = 0.f;
            #pragma unroll
            for (int k = 0; k < FOUT; k++) su += W2[t * FOUT + k] * b2[k];
            g_u[t] = su;
        }
        if (t == 0) {
            float sc = 0.f;
            #pragma unroll
            for (int k = 0; k < FOUT; k++) sc += b2[k] * b2[k];
            g_c = sc;
        }
    }
}

// in-degree over dst (2 edges/thread, int2 loads)
__global__ void k_deg(const int* __restrict__ dst) {
    int t = blockIdx.x * blockDim.x + threadIdx.x;
    int e = t * 2;
    if (e >= EE) return;
    int2 d2 = *(const int2*)(dst + e);
    atomicAdd(&g_deg[d2.x], 1);
    atomicAdd(&g_deg[d2.y], 1);
}

// ---- 3-step exclusive prefix scan of g_deg into g_rowptr ----
__global__ void k_scan1() {
    __shared__ int sh[512];
    int tid = threadIdx.x;
    int i = blockIdx.x * 512 + tid;
    int v = (i < NN) ? g_deg[i] : 0;
    sh[tid] = v;
    __syncthreads();
    #pragma unroll
    for (int off = 1; off < 512; off <<= 1) {
        int t = (tid >= off) ? sh[tid - off] : 0;
        __syncthreads();
        sh[tid] += t;
        __syncthreads();
    }
    if (i < NN) g_rowptr[i] = sh[tid] - v;       // exclusive within block
    if (tid == 511) g_bsum[blockIdx.x] = sh[511];
}

__global__ void k_scan2() {
    __shared__ int sh[256];
    int tid = threadIdx.x;
    int v = (tid < NB) ? g_bsum[tid] : 0;
    sh[tid] = v;
    __syncthreads();
    #pragma unroll
    for (int off = 1; off < 256; off <<= 1) {
        int t = (tid >= off) ? sh[tid - off] : 0;
        __syncthreads();
        sh[tid] += t;
        __syncthreads();
    }
    if (tid < NB) g_boff[tid] = sh[tid] - v;     // exclusive block offsets
}

// add block offsets; also compute dinv here (fused)
__global__ void k_scan3() {
    int i = blockIdx.x * blockDim.x + threadIdx.x;
    if (i < NN) {
        g_rowptr[i] += g_boff[i >> 9];
        g_dinv[i] = rsqrtf((float)g_deg[i] + 1.0f);
    }
    if (i == 0) g_rowptr[NN] = EE;
}

// CSR fill: csr[rowptr[d] + pos] = src   (2 edges/thread, int2 loads)
__global__ void k_fill(const int* __restrict__ src, const int* __restrict__ dst) {
    int t = blockIdx.x * blockDim.x + threadIdx.x;
    int e = t * 2;
    if (e >= EE) return;
    int2 s2 = *(const int2*)(src + e);
    int2 d2 = *(const int2*)(dst + e);
    int p0 = atomicAdd(&g_cursor[d2.x], 1);
    g_csr[g_rowptr[d2.x] + p0] = s2.x;
    int p1 = atomicAdd(&g_cursor[d2.y], 1);
    g_csr[g_rowptr[d2.y] + p1] = s2.y;
}

// hs = (x @ W1) * dinv[row].   One warp computes 4 rows; W1 staged in smem
// with pad-17 layout so the (k = lane + 32t) access pattern is conflict-free.
__global__ void k_gemm1(const float* __restrict__ x, const float* __restrict__ W1) {
    __shared__ float w[FIN * 17];
    int tid = threadIdx.x;
    for (int i = tid; i < FIN * FH; i += blockDim.x) {
        int k = i >> 4, j = i & 15;
        w[k * 17 + j] = W1[i];
    }
    __syncthreads();

    int warp = tid >> 5, lane = tid & 31;
    int row0 = (blockIdx.x * (blockDim.x >> 5) + warp) * 4;
    if (row0 >= NN) return;

    float acc[4][16];
    #pragma unroll
    for (int r = 0; r < 4; r++)
        #pragma unroll
        for (int j = 0; j < 16; j++) acc[r][j] = 0.f;

    const float* x0 = x + (size_t)row0 * FIN;
    #pragma unroll
    for (int t = 0; t < 8; t++) {
        int k = lane + 32 * t;
        float xv0 = x0[k];
        float xv1 = x0[FIN + k];
        float xv2 = x0[2 * FIN + k];
        float xv3 = x0[3 * FIN + k];
        #pragma unroll
        for (int j = 0; j < 16; j++) {
            float wv = w[k * 17 + j];
            acc[0][j] += xv0 * wv;
            acc[1][j] += xv1 * wv;
            acc[2][j] += xv2 * wv;
            acc[3][j] += xv3 * wv;
        }
    }
    #pragma unroll
    for (int r = 0; r < 4; r++)
        #pragma unroll
        for (int j = 0; j < 16; j++) {
            float v = acc[r][j];
            v += __shfl_xor_sync(0xffffffffu, v, 16);
            v += __shfl_xor_sync(0xffffffffu, v, 8);
            v += __shfl_xor_sync(0xffffffffu, v, 4);
            v += __shfl_xor_sync(0xffffffffu, v, 2);
            v += __shfl_xor_sync(0xffffffffu, v, 1);
            acc[r][j] = v;
        }
    if (lane < 16) {
        #pragma unroll
        for (int r = 0; r < 4; r++) {
            int row = row0 + r;
            float o = 0.f;
            #pragma unroll
            for (int j = 0; j < 16; j++)
                if (lane == j) o = acc[r][j];
            g_hs[row * FH + lane] = o * g_dinv[row];
        }
    }
}

// Layer-1 pull gather + epilogue fused.
// One warp per node: lane = (neighbor parity)*16 + feature j.
// Main loop keeps 4 independent idx+row load chains in flight per half.
// zs = relu(dinv*(sum_neighbors hs + hs[self]) + b1) * dinv
__global__ void k_gather1(const float* __restrict__ b1) {
    int warp = (blockIdx.x * blockDim.x + threadIdx.x) >> 5;
    int lane = threadIdx.x & 31;
    if (warp >= NN) return;
    int d = warp;
    int beg = g_rowptr[d], end = g_rowptr[d + 1];
    int j = lane & 15;
    int half = lane >> 4;

    float a0 = 0.f, a1 = 0.f, a2 = 0.f, a3 = 0.f;
    int k = beg + half;
    for (; k + 6 < end; k += 8) {
        int s0 = g_csr[k], s1 = g_csr[k + 2], s2 = g_csr[k + 4], s3 = g_csr[k + 6];
        a0 += g_hs[s0 * FH + j];
        a1 += g_hs[s1 * FH + j];
        a2 += g_hs[s2 * FH + j];
        a3 += g_hs[s3 * FH + j];
    }
    for (; k < end; k += 2) a0 += g_hs[g_csr[k] * FH + j];
    float acc = (a0 + a1) + (a2 + a3);
    acc += __shfl_xor_sync(0xffffffffu, acc, 16);

    if (lane < 16) {
        float di = g_dinv[d];
        float z = fmaxf(di * (acc + g_hs[d * FH + j]) + b1[j], 0.f);
        g_zs[d * FH + j] = z * di;
    }
}

// Layer-2 pull gather + full epilogue fused:
// a2 = dinv*(sum zs + zs[self]);  q = G a2;  p = a2.u + c/2
__global__ void k_gather2() {
    __shared__ float Gs[FH * FH];
    __shared__ float us[FH];
    __shared__ float cs;
    int tid = threadIdx.x;
    if (tid < FH * FH) Gs[tid] = g_G[tid];
    if (tid < FH) us[tid] = g_u[tid];
    if (tid == 0) cs = g_c;
    __syncthreads();

    int warp = (blockIdx.x * blockDim.x + tid) >> 5;
    int lane = tid & 31;
    if (warp >= NN) return;
    int d = warp;
    int beg = g_rowptr[d], end = g_rowptr[d + 1];
    int j = lane & 15;
    int half = lane >> 4;

    float a0 = 0.f, a1 = 0.f, a2v = 0.f, a3 = 0.f;
    int k = beg + half;
    for (; k + 6 < end; k += 8) {
        int s0 = g_csr[k], s1 = g_csr[k + 2], s2 = g_csr[k + 4], s3 = g_csr[k + 6];
        a0  += g_zs[s0 * FH + j];
        a1  += g_zs[s1 * FH + j];
        a2v += g_zs[s2 * FH + j];
        a3  += g_zs[s3 * FH + j];
    }
    for (; k < end; k += 2) a0 += g_zs[g_csr[k] * FH + j];
    float acc = (a0 + a1) + (a2v + a3);
    acc += __shfl_xor_sync(0xffffffffu, acc, 16);   // both halves hold full sum

    float di = g_dinv[d];
    float a = di * (acc + g_zs[d * FH + j]);        // a2[j] (valid on all lanes)

    // q[j] = sum_k G[j][k] * a[k]  via lane broadcast
    float q = 0.f;
    #pragma unroll
    for (int kk = 0; kk < FH; kk++) {
        float ak = __shfl_sync(0xffffffffu, a, kk);
        q += Gs[j * FH + kk] * ak;
    }
    // p = sum_j a[j]*u[j] + c/2
    float pv = a * us[j];
    pv += __shfl_xor_sync(0xffffffffu, pv, 8);
    pv += __shfl_xor_sync(0xffffffffu, pv, 4);
    pv += __shfl_xor_sync(0xffffffffu, pv, 2);
    pv += __shfl_xor_sync(0xffffffffu, pv, 1);

    if (lane < 16) {
        g_a2[d * FH + j] = a;
        g_q [d * FH + j] = q;
        if (lane == 0) g_p[d] = pv + 0.5f * cs;
    }
}

// logits[e] = q[s] . a2[d] + p[s] + p[d]
__global__ void k_logits(const int* __restrict__ pos, const int* __restrict__ neg,
                         float* __restrict__ out) {
    int e = blockIdx.x * blockDim.x + threadIdx.x;
    if (e >= 2 * ETEST) return;
    int s, d;
    if (e < ETEST) { s = pos[e];         d = pos[ETEST + e]; }
    else           { s = neg[e - ETEST]; d = neg[ETEST + (e - ETEST)]; }
    const float4* qs = (const float4*)(g_q  + (size_t)s * FH);
    const float4* ad = (const float4*)(g_a2 + (size_t)d * FH);
    float acc = g_p[s] + g_p[d];
    #pragma unroll
    for (int v = 0; v < 4; v++) {
        float4 qv = qs[v], av = ad[v];
        acc += qv.x * av.x + qv.y * av.y + qv.z * av.z + qv.w * av.w;
    }
    out[e] = acc;
}

// ---------------- launch ----------------
extern "C" void kernel_launch(void* const* d_in, const int* in_sizes, int n_in,
                              void* d_out, int out_size) {
    // Resolve inputs BY SIZE (robust to metadata ordering).
    const float* x  = nullptr; const int* tei = nullptr;
    const int*   pos = nullptr; const int* neg = nullptr;
    const float* W1 = nullptr; const float* b1 = nullptr;
    const float* W2 = nullptr; const float* b2 = nullptr;
    for (int i = 0; i < n_in; i++) {
        int sz = in_sizes[i];
        const void* p = d_in[i];
        if      (sz == NN * FIN)   x   = (const float*)p;
        else if (sz == 2 * EE)     tei = (const int*)p;
        else if (sz == 2 * ETEST) { if (!pos) pos = (const int*)p; else neg = (const int*)p; }
        else if (sz == FIN * FH)   W1  = (const float*)p;
        else if (sz == FH)         b1  = (const float*)p;
        else if (sz == FH * FOUT)  W2  = (const float*)p;
        else if (sz == FOUT)       b2  = (const float*)p;
    }
    float* out = (float*)d_out;

    const int* src = tei;
    const int* dst = tei + EE;

    k_zero   <<<(NN + 255) / 256, 256>>>();
    k_guc    <<<1, 256>>>(W2, b2);
    k_deg    <<<(EE / 2 + 255) / 256, 256>>>(dst);
    k_scan1  <<<NB, 512>>>();
    k_scan2  <<<1, 256>>>();
    k_scan3  <<<(NN + 255) / 256, 256>>>();
    k_fill   <<<(EE / 2 + 255) / 256, 256>>>(src, dst);
    k_gemm1  <<<(NN / 4 + 7) / 8, 256>>>(x, W1);          // 8 warps/block, 4 rows/warp
    k_gather1<<<(NN * 32 + 255) / 256, 256>>>(b1);        // 1 warp / node
    k_gather2<<<(NN * 32 + 255) / 256, 256>>>();
    k_logits <<<(2 * ETEST + 255) / 256, 256>>>(pos, neg, out);
}

// round 11
// speedup vs baseline: 2.6421x; 1.0971x over previous
#include <cuda_runtime.h>
#include <cuda_bf16.h>
#include <cstdint>

// Problem constants (fixed by the reference setup)
#define NN     100000
#define EE     3200000
#define ETEST  500000
#define FIN    256
#define FH     16
#define FOUT   64
#define NB     196        // scan blocks: ceil(NN/512)

// ---------------- device scratch (no allocs allowed) ----------------
__device__ __align__(256) int   g_deg   [NN];
__device__ __align__(256) int   g_cursor[NN];
__device__ __align__(256) int   g_rowptr[NN + 1];
__device__ __align__(256) int   g_bsum  [NB];
__device__ __align__(256) int   g_boff  [NB];
__device__ __align__(256) int   g_csr   [EE];
__device__ __align__(256) float g_dinv[NN];
__device__ __align__(256) float g_hs [NN * FH];   // (x@W1) * dinv[row]
__device__ __align__(256) float g_zs [NN * FH];   // relu(z1) * dinv[row]
__device__ __align__(256) float g_a2 [NN * FH];   // layer-2 node features (16-dim)
__device__ __align__(256) float g_q  [NN * FH];   // q = G @ a2
__device__ __align__(256) float g_p  [NN];        // p = a2 . u + c/2
__device__ __align__(256) float g_G  [FH * FH];   // W2 W2^T (symmetric)
__device__ __align__(256) float g_u  [FH];        // W2 b2
__device__ float g_c;                             // ||b2||^2

// ---------------- kernels ----------------

// block 0: G/u/c precompute; other blocks: zero deg+cursor
__global__ void k_init(const float* __restrict__ W2, const float* __restrict__ b2) {
    if (blockIdx.x == 0) {
        int t = threadIdx.x;
        if (t < FH * FH) {
            int i = t >> 4, j = t & 15;
            float s = 0.f;
            #pragma unroll
            for (int k = 0; k < FOUT; k++) s += W2[i * FOUT + k] * W2[j * FOUT + k];
            g_G[t] = s;
            if (t < FH) {
                float su = 0.f;
                #pragma unroll
                for (int k = 0; k < FOUT; k++) su += W2[t * FOUT + k] * b2[k];
                g_u[t] = su;
            }
            if (t == 0) {
                float sc = 0.f;
                #pragma unroll
                for (int k = 0; k < FOUT; k++) sc += b2[k] * b2[k];
                g_c = sc;
            }
        }
    } else {
        int t = (blockIdx.x - 1) * blockDim.x + threadIdx.x;
        if (t < NN) { g_deg[t] = 0; g_cursor[t] = 0; }
    }
}

// in-degree over dst (2 edges/thread, int2 loads)
__global__ void k_deg(const int* __restrict__ dst) {
    int t = blockIdx.x * blockDim.x + threadIdx.x;
    int e = t * 2;
    if (e >= EE) return;
    int2 d2 = *(const int2*)(dst + e);
    atomicAdd(&g_deg[d2.x], 1);
    atomicAdd(&g_deg[d2.y], 1);
}

// ---- 3-step exclusive prefix scan of g_deg into g_rowptr ----
__global__ void k_scan1() {
    __shared__ int sh[512];
    int tid = threadIdx.x;
    int i = blockIdx.x * 512 + tid;
    int v = (i < NN) ? g_deg[i] : 0;
    sh[tid] = v;
    __syncthreads();
    #pragma unroll
    for (int off = 1; off < 512; off <<= 1) {
        int t = (tid >= off) ? sh[tid - off] : 0;
        __syncthreads();
        sh[tid] += t;
        __syncthreads();
    }
    if (i < NN) g_rowptr[i] = sh[tid] - v;       // exclusive within block
    if (tid == 511) g_bsum[blockIdx.x] = sh[511];
}

__global__ void k_scan2() {
    __shared__ int sh[256];
    int tid = threadIdx.x;
    int v = (tid < NB) ? g_bsum[tid] : 0;
    sh[tid] = v;
    __syncthreads();
    #pragma unroll
    for (int off = 1; off < 256; off <<= 1) {
        int t = (tid >= off) ? sh[tid - off] : 0;
        __syncthreads();
        sh[tid] += t;
        __syncthreads();
    }
    if (tid < NB) g_boff[tid] = sh[tid] - v;     // exclusive block offsets
}

// add block offsets; also compute dinv here (fused)
__global__ void k_scan3() {
    int i = blockIdx.x * blockDim.x + threadIdx.x;
    if (i < NN) {
        g_rowptr[i] += g_boff[i >> 9];
        g_dinv[i] = rsqrtf((float)g_deg[i] + 1.0f);
    }
    if (i == 0) g_rowptr[NN] = EE;
}

// CSR fill: csr[rowptr[d] + pos] = src   (2 edges/thread, int2 loads)
__global__ void k_fill(const int* __restrict__ src, const int* __restrict__ dst) {
    int t = blockIdx.x * blockDim.x + threadIdx.x;
    int e = t * 2;
    if (e >= EE) return;
    int2 s2 = *(const int2*)(src + e);
    int2 d2 = *(const int2*)(dst + e);
    int p0 = atomicAdd(&g_cursor[d2.x], 1);
    g_csr[g_rowptr[d2.x] + p0] = s2.x;
    int p1 = atomicAdd(&g_cursor[d2.y], 1);
    g_csr[g_rowptr[d2.y] + p1] = s2.y;
}

// hs = (x @ W1) * dinv[row].   One warp computes 4 rows; W1 staged in smem
// with pad-17 layout so the (k = lane + 32t) access pattern is conflict-free.
__global__ void k_gemm1(const float* __restrict__ x, const float* __restrict__ W1) {
    __shared__ float w[FIN * 17];
    int tid = threadIdx.x;
    for (int i = tid; i < FIN * FH; i += blockDim.x) {
        int k = i >> 4, j = i & 15;
        w[k * 17 + j] = W1[i];
    }
    __syncthreads();

    int warp = tid >> 5, lane = tid & 31;
    int row0 = (blockIdx.x * (blockDim.x >> 5) + warp) * 4;
    if (row0 >= NN) return;

    float acc[4][16];
    #pragma unroll
    for (int r = 0; r < 4; r++)
        #pragma unroll
        for (int j = 0; j < 16; j++) acc[r][j] = 0.f;

    const float* x0 = x + (size_t)row0 * FIN;
    #pragma unroll
    for (int t = 0; t < 8; t++) {
        int k = lane + 32 * t;
        float xv0 = x0[k];
        float xv1 = x0[FIN + k];
        float xv2 = x0[2 * FIN + k];
        float xv3 = x0[3 * FIN + k];
        #pragma unroll
        for (int j = 0; j < 16; j++) {
            float wv = w[k * 17 + j];
            acc[0][j] += xv0 * wv;
            acc[1][j] += xv1 * wv;
            acc[2][j] += xv2 * wv;
            acc[3][j] += xv3 * wv;
        }
    }
    #pragma unroll
    for (int r = 0; r < 4; r++)
        #pragma unroll
        for (int j = 0; j < 16; j++) {
            float v = acc[r][j];
            v += __shfl_xor_sync(0xffffffffu, v, 16);
            v += __shfl_xor_sync(0xffffffffu, v, 8);
            v += __shfl_xor_sync(0xffffffffu, v, 4);
            v += __shfl_xor_sync(0xffffffffu, v, 2);
            v += __shfl_xor_sync(0xffffffffu, v, 1);
            acc[r][j] = v;
        }
    if (lane < 16) {
        #pragma unroll
        for (int r = 0; r < 4; r++) {
            int row = row0 + r;
            float o = 0.f;
            #pragma unroll
            for (int j = 0; j < 16; j++)
                if (lane == j) o = acc[r][j];
            g_hs[row * FH + lane] = o * g_dinv[row];
        }
    }
}

// Layer-1 gather, vectorized: lane = {vec = lane&3 (float4 of row),
// slot = lane>>2 (neighbor 0..7)}.  Per iteration: 1 LDG.32 (8 idx) +
// 1 LDG.128 (8 rows).  Butterfly over slots; lanes 0-3 write float4.
__global__ void k_gather1(const float* __restrict__ b1) {
    int warp = (blockIdx.x * blockDim.x + threadIdx.x) >> 5;
    int lane = threadIdx.x & 31;
    if (warp >= NN) return;
    int d = warp;
    int beg = g_rowptr[d], end = g_rowptr[d + 1];
    int vec = lane & 3, slot = lane >> 2;
    const float4* hv = (const float4*)g_hs;

    float4 acc = make_float4(0.f, 0.f, 0.f, 0.f);
    for (int base = beg; base < end; base += 8) {
        int kk = base + slot;
        if (kk < end) {
            int s = g_csr[kk];
            float4 v = hv[s * 4 + vec];
            acc.x += v.x; acc.y += v.y; acc.z += v.z; acc.w += v.w;
        }
    }
    #pragma unroll
    for (int m = 4; m < 32; m <<= 1) {
        acc.x += __shfl_xor_sync(0xffffffffu, acc.x, m);
        acc.y += __shfl_xor_sync(0xffffffffu, acc.y, m);
        acc.z += __shfl_xor_sync(0xffffffffu, acc.z, m);
        acc.w += __shfl_xor_sync(0xffffffffu, acc.w, m);
    }
    if (lane < 4) {
        float di = g_dinv[d];
        float4 self = hv[d * 4 + lane];
        float4 b = ((const float4*)b1)[lane];
        float4 z;
        z.x = fmaxf(di * (acc.x + self.x) + b.x, 0.f) * di;
        z.y = fmaxf(di * (acc.y + self.y) + b.y, 0.f) * di;
        z.z = fmaxf(di * (acc.z + self.z) + b.z, 0.f) * di;
        z.w = fmaxf(di * (acc.w + self.w) + b.w, 0.f) * di;
        ((float4*)g_zs)[d * 4 + lane] = z;
    }
}

// Layer-2 gather (same vectorized pattern) + full epilogue:
// a2 = dinv*(sum zs + zs[self]);  q = G a2 (G symmetric -> conflict-free);
// p = a2.u + c/2
__global__ void k_gather2() {
    __shared__ float Gs[FH * FH];
    __shared__ float us[FH];
    __shared__ float cs;
    int tid = threadIdx.x;
    if (tid < FH * FH) Gs[tid] = g_G[tid];
    if (tid < FH) us[tid] = g_u[tid];
    if (tid == 0) cs = g_c;
    __syncthreads();

    int warp = (blockIdx.x * blockDim.x + tid) >> 5;
    int lane = tid & 31;
    if (warp >= NN) return;
    int d = warp;
    int beg = g_rowptr[d], end = g_rowptr[d + 1];
    int vec = lane & 3, slot = lane >> 2;
    const float4* zv = (const float4*)g_zs;

    float4 acc = make_float4(0.f, 0.f, 0.f, 0.f);
    for (int base = beg; base < end; base += 8) {
        int kk = base + slot;
        if (kk < end) {
            int s = g_csr[kk];
            float4 v = zv[s * 4 + vec];
            acc.x += v.x; acc.y += v.y; acc.z += v.z; acc.w += v.w;
        }
    }
    #pragma unroll
    for (int m = 4; m < 32; m <<= 1) {
        acc.x += __shfl_xor_sync(0xffffffffu, acc.x, m);
        acc.y += __shfl_xor_sync(0xffffffffu, acc.y, m);
        acc.z += __shfl_xor_sync(0xffffffffu, acc.z, m);
        acc.w += __shfl_xor_sync(0xffffffffu, acc.w, m);
    }
    // every lane now holds the full sum for its vec's 4 features
    float di = g_dinv[d];
    float4 self = zv[d * 4 + vec];
    float4 a4;
    a4.x = di * (acc.x + self.x);
    a4.y = di * (acc.y + self.y);
    a4.z = di * (acc.z + self.z);
    a4.w = di * (acc.w + self.w);

    // distribute all 16 a values to every lane
    // a[f] lives in component (f&3) of any lane with vec == f>>2; lane f>>2 works.
    float comp[4] = {a4.x, a4.y, a4.z, a4.w};
    float ak[16];
    #pragma unroll
    for (int f = 0; f < 16; f++)
        ak[f] = __shfl_sync(0xffffffffu, comp[f & 3], f >> 2);

    int j = lane & 15;
    float q = 0.f;
    #pragma unroll
    for (int k = 0; k < FH; k++)
        q += Gs[k * FH + j] * ak[k];          // G symmetric: conflict-free LDS
    float p = 0.5f * cs;
    #pragma unroll
    for (int k = 0; k < FH; k++)
        p += ak[k] * us[k];

    if (lane < 4) ((float4*)g_a2)[d * 4 + lane] = a4;
    if (lane < 16) {
        g_q[d * FH + j] = q;
        if (lane == 0) g_p[d] = p;
    }
}

// logits[e] = q[s] . a2[d] + p[s] + p[d]
__global__ void k_logits(const int* __restrict__ pos, const int* __restrict__ neg,
                         float* __restrict__ out) {
    int e = blockIdx.x * blockDim.x + threadIdx.x;
    if (e >= 2 * ETEST) return;
    int s, d;
    if (e < ETEST) { s = pos[e];         d = pos[ETEST + e]; }
    else           { s = neg[e - ETEST]; d = neg[ETEST + (e - ETEST)]; }
    const float4* qs = (const float4*)(g_q  + (size_t)s * FH);
    const float4* ad = (const float4*)(g_a2 + (size_t)d * FH);
    float acc = g_p[s] + g_p[d];
    #pragma unroll
    for (int v = 0; v < 4; v++) {
        float4 qv = qs[v], av = ad[v];
        acc += qv.x * av.x + qv.y * av.y + qv.z * av.z + qv.w * av.w;
    }
    out[e] = acc;
}

// ---------------- launch ----------------
extern "C" void kernel_launch(void* const* d_in, const int* in_sizes, int n_in,
                              void* d_out, int out_size) {
    // Resolve inputs BY SIZE (robust to metadata ordering).
    const float* x  = nullptr; const int* tei = nullptr;
    const int*   pos = nullptr; const int* neg = nullptr;
    const float* W1 = nullptr; const float* b1 = nullptr;
    const float* W2 = nullptr; const float* b2 = nullptr;
    for (int i = 0; i < n_in; i++) {
        int sz = in_sizes[i];
        const void* p = d_in[i];
        if      (sz == NN * FIN)   x   = (const float*)p;
        else if (sz == 2 * EE)     tei = (const int*)p;
        else if (sz == 2 * ETEST) { if (!pos) pos = (const int*)p; else neg = (const int*)p; }
        else if (sz == FIN * FH)   W1  = (const float*)p;
        else if (sz == FH)         b1  = (const float*)p;
        else if (sz == FH * FOUT)  W2  = (const float*)p;
        else if (sz == FOUT)       b2  = (const float*)p;
    }
    float* out = (float*)d_out;

    const int* src = tei;
    const int* dst = tei + EE;

    k_init   <<<1 + (NN + 255) / 256, 256>>>(W2, b2);
    k_deg    <<<(EE / 2 + 255) / 256, 256>>>(dst);
    k_scan1  <<<NB, 512>>>();
    k_scan2  <<<1, 256>>>();
    k_scan3  <<<(NN + 255) / 256, 256>>>();
    k_fill   <<<(EE / 2 + 255) / 256, 256>>>(src, dst);
    k_gemm1  <<<(NN / 4 + 7) / 8, 256>>>(x, W1);          // 8 warps/block, 4 rows/warp
    k_gather1<<<(NN * 32 + 255) / 256, 256>>>(b1);        // 1 warp / node
    k_gather2<<<(NN * 32 + 255) / 256, 256>>>();
    k_logits <<<(2 * ETEST + 255) / 256, 256>>>(pos, neg, out);
}

// round 12
// speedup vs baseline: 2.6705x; 1.0107x over previous
#include <cuda_runtime.h>
#include <cuda_bf16.h>
#include <cstdint>

// Problem constants (fixed by the reference setup)
#define NN     100000
#define EE     3200000
#define ETEST  500000
#define FIN    256
#define FH     16
#define FOUT   64
#define NB     196        // scan blocks: ceil(NN/512)

// ---------------- device scratch (no allocs allowed) ----------------
// Static zero-init gives deg/cursor = 0 on first run; kernels restore the
// zeros at end of every execution (self-cleaning), so graph replays see
// identical starting state.
__device__ __align__(256) int   g_deg   [NN];
__device__ __align__(256) int   g_cursor[NN];
__device__ __align__(256) int   g_rowptr[NN + 1];
__device__ __align__(256) int   g_bsum  [NB];
__device__ __align__(256) int   g_csr   [EE];
__device__ __align__(256) float g_dinv[NN];
__device__ __align__(256) float g_hs [NN * FH];   // (x@W1) * dinv[row]
__device__ __align__(256) float g_zs [NN * FH];   // relu(z1) * dinv[row]
__device__ __align__(256) float g_a2 [NN * FH];   // layer-2 node features (16-dim)
__device__ __align__(256) float g_q  [NN * FH];   // q = G @ a2
__device__ __align__(256) float g_p  [NN];        // p = a2 . u + c/2
__device__ __align__(256) float g_G  [FH * FH];   // W2 W2^T (symmetric)
__device__ __align__(256) float g_u  [FH];        // W2 b2
__device__ float g_c;                             // ||b2||^2

// ---------------- kernels ----------------

// block 0: G/u/c precompute.  blocks 1..: in-degree over dst, 4 edges/thread.
__global__ void k_deginit(const int* __restrict__ dst,
                          const float* __restrict__ W2,
                          const float* __restrict__ b2) {
    if (blockIdx.x == 0) {
        int t = threadIdx.x;
        if (t < FH * FH) {
            int i = t >> 4, j = t & 15;
            float s = 0.f;
            #pragma unroll
            for (int k = 0; k < FOUT; k++) s += W2[i * FOUT + k] * W2[j * FOUT + k];
            g_G[t] = s;
            if (t < FH) {
                float su = 0.f;
                #pragma unroll
                for (int k = 0; k < FOUT; k++) su += W2[t * FOUT + k] * b2[k];
                g_u[t] = su;
            }
            if (t == 0) {
                float sc = 0.f;
                #pragma unroll
                for (int k = 0; k < FOUT; k++) sc += b2[k] * b2[k];
                g_c = sc;
            }
        }
    } else {
        int e = ((blockIdx.x - 1) * blockDim.x + threadIdx.x) * 4;
        if (e >= EE) return;
        int4 d4 = *(const int4*)(dst + e);
        atomicAdd(&g_deg[d4.x], 1);
        atomicAdd(&g_deg[d4.y], 1);
        atomicAdd(&g_deg[d4.z], 1);
        atomicAdd(&g_deg[d4.w], 1);
    }
}

// block-local exclusive prefix scan of g_deg into g_rowptr, block sums to g_bsum
__global__ void k_scan1() {
    __shared__ int sh[512];
    int tid = threadIdx.x;
    int i = blockIdx.x * 512 + tid;
    int v = (i < NN) ? g_deg[i] : 0;
    sh[tid] = v;
    __syncthreads();
    #pragma unroll
    for (int off = 1; off < 512; off <<= 1) {
        int t = (tid >= off) ? sh[tid - off] : 0;
        __syncthreads();
        sh[tid] += t;
        __syncthreads();
    }
    if (i < NN) g_rowptr[i] = sh[tid] - v;       // exclusive within block
    if (tid == 511) g_bsum[blockIdx.x] = sh[511];
}

// Every block redundantly scans the 196 block sums (inclusive) in smem, then
// adds its group's exclusive offset to rowptr.  Also: dinv, deg reset (for
// next replay), rowptr[NN].
__global__ void k_scan3() {
    __shared__ int sh[256];
    int tid = threadIdx.x;
    int v = (tid < NB) ? g_bsum[tid] : 0;
    sh[tid] = v;
    __syncthreads();
    #pragma unroll
    for (int off = 1; off < 256; off <<= 1) {
        int t = (tid >= off) ? sh[tid - off] : 0;
        __syncthreads();
        sh[tid] += t;
        __syncthreads();
    }
    int g = blockIdx.x >> 1;                     // 512-group of this block
    int S = (g == 0) ? 0 : sh[g - 1];            // exclusive offset (broadcast)
    int i = blockIdx.x * 256 + tid;
    if (i < NN) {
        g_rowptr[i] += S;
        g_dinv[i] = rsqrtf((float)g_deg[i] + 1.0f);
        g_deg[i] = 0;                            // self-clean for next replay
    }
    if (i == 0) g_rowptr[NN] = EE;
}

// CSR fill: csr[rowptr[d] + pos] = src   (4 edges/thread, int4 loads)
__global__ void k_fill(const int* __restrict__ src, const int* __restrict__ dst) {
    int e = (blockIdx.x * blockDim.x + threadIdx.x) * 4;
    if (e >= EE) return;
    int4 s4 = *(const int4*)(src + e);
    int4 d4 = *(const int4*)(dst + e);
    int p0 = atomicAdd(&g_cursor[d4.x], 1);
    g_csr[g_rowptr[d4.x] + p0] = s4.x;
    int p1 = atomicAdd(&g_cursor[d4.y], 1);
    g_csr[g_rowptr[d4.y] + p1] = s4.y;
    int p2 = atomicAdd(&g_cursor[d4.z], 1);
    g_csr[g_rowptr[d4.z] + p2] = s4.z;
    int p3 = atomicAdd(&g_cursor[d4.w], 1);
    g_csr[g_rowptr[d4.w] + p3] = s4.w;
}

// hs = (x @ W1) * dinv[row].   One warp computes 4 rows; W1 staged in smem
// with pad-17 layout so the (k = lane + 32t) access pattern is conflict-free.
__global__ void k_gemm1(const float* __restrict__ x, const float* __restrict__ W1) {
    __shared__ float w[FIN * 17];
    int tid = threadIdx.x;
    for (int i = tid; i < FIN * FH; i += blockDim.x) {
        int k = i >> 4, j = i & 15;
        w[k * 17 + j] = W1[i];
    }
    __syncthreads();

    int warp = tid >> 5, lane = tid & 31;
    int row0 = (blockIdx.x * (blockDim.x >> 5) + warp) * 4;
    if (row0 >= NN) return;

    float acc[4][16];
    #pragma unroll
    for (int r = 0; r < 4; r++)
        #pragma unroll
        for (int j = 0; j < 16; j++) acc[r][j] = 0.f;

    const float* x0 = x + (size_t)row0 * FIN;
    #pragma unroll
    for (int t = 0; t < 8; t++) {
        int k = lane + 32 * t;
        float xv0 = x0[k];
        float xv1 = x0[FIN + k];
        float xv2 = x0[2 * FIN + k];
        float xv3 = x0[3 * FIN + k];
        #pragma unroll
        for (int j = 0; j < 16; j++) {
            float wv = w[k * 17 + j];
            acc[0][j] += xv0 * wv;
            acc[1][j] += xv1 * wv;
            acc[2][j] += xv2 * wv;
            acc[3][j] += xv3 * wv;
        }
    }
    #pragma unroll
    for (int r = 0; r < 4; r++)
        #pragma unroll
        for (int j = 0; j < 16; j++) {
            float v = acc[r][j];
            v += __shfl_xor_sync(0xffffffffu, v, 16);
            v += __shfl_xor_sync(0xffffffffu, v, 8);
            v += __shfl_xor_sync(0xffffffffu, v, 4);
            v += __shfl_xor_sync(0xffffffffu, v, 2);
            v += __shfl_xor_sync(0xffffffffu, v, 1);
            acc[r][j] = v;
        }
    if (lane < 16) {
        #pragma unroll
        for (int r = 0; r < 4; r++) {
            int row = row0 + r;
            float o = 0.f;
            #pragma unroll
            for (int j = 0; j < 16; j++)
                if (lane == j) o = acc[r][j];
            g_hs[row * FH + lane] = o * g_dinv[row];
        }
    }
}

// Layer-1 gather, vectorized: lane = {vec = lane&3, slot = lane>>2}.
// Guard-free full iterations + one guarded remainder.  Lane 0 self-cleans
// g_cursor for the next replay.
__global__ void k_gather1(const float* __restrict__ b1) {
    int warp = (blockIdx.x * blockDim.x + threadIdx.x) >> 5;
    int lane = threadIdx.x & 31;
    if (warp >= NN) return;
    int d = warp;
    int beg = g_rowptr[d], end = g_rowptr[d + 1];
    int vec = lane & 3, slot = lane >> 2;
    const float4* hv = (const float4*)g_hs;

    int nfull = beg + ((end - beg) & ~7);
    float4 acc = make_float4(0.f, 0.f, 0.f, 0.f);
    int base = beg;
    for (; base < nfull; base += 8) {
        int s = g_csr[base + slot];
        float4 v = hv[s * 4 + vec];
        acc.x += v.x; acc.y += v.y; acc.z += v.z; acc.w += v.w;
    }
    if (base + slot < end) {
        int s = g_csr[base + slot];
        float4 v = hv[s * 4 + vec];
        acc.x += v.x; acc.y += v.y; acc.z += v.z; acc.w += v.w;
    }
    #pragma unroll
    for (int m = 4; m < 32; m <<= 1) {
        acc.x += __shfl_xor_sync(0xffffffffu, acc.x, m);
        acc.y += __shfl_xor_sync(0xffffffffu, acc.y, m);
        acc.z += __shfl_xor_sync(0xffffffffu, acc.z, m);
        acc.w += __shfl_xor_sync(0xffffffffu, acc.w, m);
    }
    if (lane == 0) g_cursor[d] = 0;              // self-clean for next replay
    if (lane < 4) {
        float di = g_dinv[d];
        float4 self = hv[d * 4 + lane];
        float4 b = ((const float4*)b1)[lane];
        float4 z;
        z.x = fmaxf(di * (acc.x + self.x) + b.x, 0.f) * di;
        z.y = fmaxf(di * (acc.y + self.y) + b.y, 0.f) * di;
        z.z = fmaxf(di * (acc.z + self.z) + b.z, 0.f) * di;
        z.w = fmaxf(di * (acc.w + self.w) + b.w, 0.f) * di;
        ((float4*)g_zs)[d * 4 + lane] = z;
    }
}

// Layer-2 gather + full epilogue:
// a2 = dinv*(sum zs + zs[self]);  q = G a2 (G symmetric -> conflict-free LDS);
// p = a2.u + c/2
__global__ void k_gather2() {
    __shared__ float Gs[FH * FH];
    __shared__ float us[FH];
    __shared__ float cs;
    int tid = threadIdx.x;
    if (tid < FH * FH) Gs[tid] = g_G[tid];
    if (tid < FH) us[tid] = g_u[tid];
    if (tid == 0) cs = g_c;
    __syncthreads();

    int warp = (blockIdx.x * blockDim.x + tid) >> 5;
    int lane = tid & 31;
    if (warp >= NN) return;
    int d = warp;
    int beg = g_rowptr[d], end = g_rowptr[d + 1];
    int vec = lane & 3, slot = lane >> 2;
    const float4* zv = (const float4*)g_zs;

    int nfull = beg + ((end - beg) & ~7);
    float4 acc = make_float4(0.f, 0.f, 0.f, 0.f);
    int base = beg;
    for (; base < nfull; base += 8) {
        int s = g_csr[base + slot];
        float4 v = zv[s * 4 + vec];
        acc.x += v.x; acc.y += v.y; acc.z += v.z; acc.w += v.w;
    }
    if (base + slot < end) {
        int s = g_csr[base + slot];
        float4 v = zv[s * 4 + vec];
        acc.x += v.x; acc.y += v.y; acc.z += v.z; acc.w += v.w;
    }
    #pragma unroll
    for (int m = 4; m < 32; m <<= 1) {
        acc.x += __shfl_xor_sync(0xffffffffu, acc.x, m);
        acc.y += __shfl_xor_sync(0xffffffffu, acc.y, m);
        acc.z += __shfl_xor_sync(0xffffffffu, acc.z, m);
        acc.w += __shfl_xor_sync(0xffffffffu, acc.w, m);
    }
    float di = g_dinv[d];
    float4 self = zv[d * 4 + vec];
    float4 a4;
    a4.x = di * (acc.x + self.x);
    a4.y = di * (acc.y + self.y);
    a4.z = di * (acc.z + self.z);
    a4.w = di * (acc.w + self.w);

    // distribute all 16 a values to every lane: a[f] from lane f>>2, comp f&3
    float comp[4] = {a4.x, a4.y, a4.z, a4.w};
    float ak[16];
    #pragma unroll
    for (int f = 0; f < 16; f++)
        ak[f] = __shfl_sync(0xffffffffu, comp[f & 3], f >> 2);

    int j = lane & 15;
    float q = 0.f;
    #pragma unroll
    for (int k = 0; k < FH; k++)
        q += Gs[k * FH + j] * ak[k];          // G symmetric: conflict-free LDS
    float p = 0.5f * cs;
    #pragma unroll
    for (int k = 0; k < FH; k++)
        p += ak[k] * us[k];

    if (lane < 4) ((float4*)g_a2)[d * 4 + lane] = a4;
    if (lane < 16) {
        g_q[d * FH + j] = q;
        if (lane == 0) g_p[d] = p;
    }
}

// logits[e] = q[s] . a2[d] + p[s] + p[d]
__global__ void k_logits(const int* __restrict__ pos, const int* __restrict__ neg,
                         float* __restrict__ out) {
    int e = blockIdx.x * blockDim.x + threadIdx.x;
    if (e >= 2 * ETEST) return;
    int s, d;
    if (e < ETEST) { s = pos[e];         d = pos[ETEST + e]; }
    else           { s = neg[e - ETEST]; d = neg[ETEST + (e - ETEST)]; }
    const float4* qs = (const float4*)(g_q  + (size_t)s * FH);
    const float4* ad = (const float4*)(g_a2 + (size_t)d * FH);
    float acc = g_p[s] + g_p[d];
    #pragma unroll
    for (int v = 0; v < 4; v++) {
        float4 qv = qs[v], av = ad[v];
        acc += qv.x * av.x + qv.y * av.y + qv.z * av.z + qv.w * av.w;
    }
    out[e] = acc;
}

// ---------------- launch ----------------
extern "C" void kernel_launch(void* const* d_in, const int* in_sizes, int n_in,
                              void* d_out, int out_size) {
    // Resolve inputs BY SIZE (robust to metadata ordering).
    const float* x  = nullptr; const int* tei = nullptr;
    const int*   pos = nullptr; const int* neg = nullptr;
    const float* W1 = nullptr; const float* b1 = nullptr;
    const float* W2 = nullptr; const float* b2 = nullptr;
    for (int i = 0; i < n_in; i++) {
        int sz = in_sizes[i];
        const void* p = d_in[i];
        if      (sz == NN * FIN)   x   = (const float*)p;
        else if (sz == 2 * EE)     tei = (const int*)p;
        else if (sz == 2 * ETEST) { if (!pos) pos = (const int*)p; else neg = (const int*)p; }
        else if (sz == FIN * FH)   W1  = (const float*)p;
        else if (sz == FH)         b1  = (const float*)p;
        else if (sz == FH * FOUT)  W2  = (const float*)p;
        else if (sz == FOUT)       b2  = (const float*)p;
    }
    float* out = (float*)d_out;

    const int* src = tei;
    const int* dst = tei + EE;

    k_deginit<<<1 + EE / 4 / 256, 256>>>(dst, W2, b2);    // 1: deg + G/u/c
    k_scan1  <<<NB, 512>>>();                              // 2
    k_scan3  <<<(NN + 255) / 256, 256>>>();                // 3: offsets+dinv+clean
    k_fill   <<<EE / 4 / 256, 256>>>(src, dst);            // 4  (profiled slot)
    k_gemm1  <<<(NN / 4 + 7) / 8, 256>>>(x, W1);           // 5
    k_gather1<<<(NN * 32 + 255) / 256, 256>>>(b1);         // 6
    k_gather2<<<(NN * 32 + 255) / 256, 256>>>();           // 7
    k_logits <<<(2 * ETEST + 255) / 256, 256>>>(pos, neg, out);  // 8
}

// round 14
// speedup vs baseline: 2.7079x; 1.0140x over previous
#include <cuda_runtime.h>
#include <cuda_bf16.h>
#include <cstdint>

// Problem constants (fixed by the reference setup)
#define NN     100000
#define EE     3200000
#define ETEST  500000
#define FIN    256
#define FH     16
#define FOUT   64
#define NB     196        // scan blocks: ceil(NN/512)

// packed dual-FMA (Blackwell f32x2 pipe; 2 FMAs per issue)
#define FMA_F32X2(d, a, b, c) \
    asm("fma.rn.f32x2 %0, %1, %2, %3;" : "=l"(d) : "l"(a), "l"(b), "l"(c))
#define PACK_F32X2(out, lo, hi) \
    asm("mov.b64 %0, {%1, %2};" : "=l"(out) : "f"(lo), "f"(hi))
#define UNPACK_F32X2(lo, hi, in) \
    asm("mov.b64 {%0, %1}, %2;" : "=f"(lo), "=f"(hi) : "l"(in))

// ---------------- device scratch (no allocs allowed) ----------------
// Static zero-init covers the first run; scan3 re-initializes cursor/deg
// every execution, so graph replays see identical starting state.
__device__ __align__(256) int   g_deg   [NN];
__device__ __align__(256) int   g_cursor[NN];     // absolute write cursors (= rowptr at fill start)
__device__ __align__(256) int   g_rowptr[NN + 1];
__device__ __align__(256) int   g_bsum  [NB];
__device__ __align__(256) int   g_csr   [EE];
__device__ __align__(256) float g_dinv[NN];
__device__ __align__(256) float g_hs [NN * FH];   // (x@W1) * dinv[row]
__device__ __align__(256) float g_zs [NN * FH];   // relu(z1) * dinv[row]
__device__ __align__(256) float g_a2 [NN * FH];   // layer-2 node features (16-dim)
__device__ __align__(256) float g_q  [NN * FH];   // q = G @ a2
__device__ __align__(256) float g_p  [NN];        // p = a2 . u + c/2
__device__ __align__(256) float g_G  [FH * FH];   // W2 W2^T (symmetric)
__device__ __align__(256) float g_u  [FH];        // W2 b2
__device__ float g_c;                             // ||b2||^2

// ---------------- kernels ----------------

// block 0: G/u/c precompute.  blocks 1..: in-degree over dst, 4 edges/thread.
__global__ void k_deginit(const int* __restrict__ dst,
                          const float* __restrict__ W2,
                          const float* __restrict__ b2) {
    if (blockIdx.x == 0) {
        int t = threadIdx.x;
        if (t < FH * FH) {
            int i = t >> 4, j = t & 15;
            float s = 0.f;
            #pragma unroll
            for (int k = 0; k < FOUT; k++) s += W2[i * FOUT + k] * W2[j * FOUT + k];
            g_G[t] = s;
            if (t < FH) {
                float su = 0.f;
                #pragma unroll
                for (int k = 0; k < FOUT; k++) su += W2[t * FOUT + k] * b2[k];
                g_u[t] = su;
            }
            if (t == 0) {
                float sc = 0.f;
                #pragma unroll
                for (int k = 0; k < FOUT; k++) sc += b2[k] * b2[k];
                g_c = sc;
            }
        }
    } else {
        int e = ((blockIdx.x - 1) * blockDim.x + threadIdx.x) * 4;
        if (e >= EE) return;
        int4 d4 = *(const int4*)(dst + e);
        atomicAdd(&g_deg[d4.x], 1);
        atomicAdd(&g_deg[d4.y], 1);
        atomicAdd(&g_deg[d4.z], 1);
        atomicAdd(&g_deg[d4.w], 1);
    }
}

// block-local exclusive prefix scan of g_deg into g_rowptr, block sums to g_bsum
__global__ void k_scan1() {
    __shared__ int sh[512];
    int tid = threadIdx.x;
    int i = blockIdx.x * 512 + tid;
    int v = (i < NN) ? g_deg[i] : 0;
    sh[tid] = v;
    __syncthreads();
    #pragma unroll
    for (int off = 1; off < 512; off <<= 1) {
        int t = (tid >= off) ? sh[tid - off] : 0;
        __syncthreads();
        sh[tid] += t;
        __syncthreads();
    }
    if (i < NN) g_rowptr[i] = sh[tid] - v;       // exclusive within block
    if (tid == 511) g_bsum[blockIdx.x] = sh[511];
}

// Every block redundantly scans the 196 block sums (inclusive) in smem, then
// adds its group's exclusive offset to rowptr.  Also: dinv, cursor := rowptr
// (absolute fill cursors), deg reset for next replay, rowptr[NN].
__global__ void k_scan3() {
    __shared__ int sh[256];
    int tid = threadIdx.x;
    int v = (tid < NB) ? g_bsum[tid] : 0;
    sh[tid] = v;
    __syncthreads();
    #pragma unroll
    for (int off = 1; off < 256; off <<= 1) {
        int t = (tid >= off) ? sh[tid - off] : 0;
        __syncthreads();
        sh[tid] += t;
        __syncthreads();
    }
    int g = blockIdx.x >> 1;                     // 512-group of this block
    int S = (g == 0) ? 0 : sh[g - 1];            // exclusive offset (broadcast)
    int i = blockIdx.x * 256 + tid;
    if (i < NN) {
        int rp = g_rowptr[i] + S;
        g_rowptr[i] = rp;
        g_cursor[i] = rp;                        // absolute cursor for k_fill
        g_dinv[i] = rsqrtf((float)g_deg[i] + 1.0f);
        g_deg[i] = 0;                            // self-clean for next replay
    }
    if (i == 0) g_rowptr[NN] = EE;
}

// CSR fill: pos = atomicAdd(cursor[d]); csr[pos] = src.
// No rowptr load (cursor is absolute).  4 edges/thread, int4 loads.
__global__ void k_fill(const int* __restrict__ src, const int* __restrict__ dst) {
    int e = (blockIdx.x * blockDim.x + threadIdx.x) * 4;
    if (e >= EE) return;
    int4 s4 = *(const int4*)(src + e);
    int4 d4 = *(const int4*)(dst + e);
    int p0 = atomicAdd(&g_cursor[d4.x], 1);
    g_csr[p0] = s4.x;
    int p1 = atomicAdd(&g_cursor[d4.y], 1);
    g_csr[p1] = s4.y;
    int p2 = atomicAdd(&g_cursor[d4.z], 1);
    g_csr[p2] = s4.z;
    int p3 = atomicAdd(&g_cursor[d4.w], 1);
    g_csr[p3] = s4.w;
}

// hs = (x @ W1) * dinv[row].   One warp computes 4 rows via packed f32x2
// FMAs (rows 0/1 and 2/3 share each FMA2).  W1 staged in smem pad-17.
__global__ void k_gemm1(const float* __restrict__ x, const float* __restrict__ W1) {
    __shared__ float w[FIN * 17];
    int tid = threadIdx.x;
    for (int i = tid; i < FIN * FH; i += blockDim.x) {
        int k = i >> 4, j = i & 15;
        w[k * 17 + j] = W1[i];
    }
    __syncthreads();

    int warp = tid >> 5, lane = tid & 31;
    int row0 = (blockIdx.x * (blockDim.x >> 5) + warp) * 4;
    if (row0 >= NN) return;

    unsigned long long acc01[16], acc23[16];
    #pragma unroll
    for (int j = 0; j < 16; j++) { acc01[j] = 0ull; acc23[j] = 0ull; }

    const float* x0 = x + (size_t)row0 * FIN;
    #pragma unroll
    for (int t = 0; t < 8; t++) {
        int k = lane + 32 * t;
        float xv0 = x0[k];
        float xv1 = x0[FIN + k];
        float xv2 = x0[2 * FIN + k];
        float xv3 = x0[3 * FIN + k];
        unsigned long long x01, x23;
        PACK_F32X2(x01, xv0, xv1);
        PACK_F32X2(x23, xv2, xv3);
        #pragma unroll
        for (int j = 0; j < 16; j++) {
            float wv = w[k * 17 + j];
            unsigned long long w2;
            PACK_F32X2(w2, wv, wv);
            FMA_F32X2(acc01[j], x01, w2, acc01[j]);
            FMA_F32X2(acc23[j], x23, w2, acc23[j]);
        }
    }
    // unpack and butterfly-reduce each output across the warp
    float acc[4][16];
    #pragma unroll
    for (int j = 0; j < 16; j++) {
        UNPACK_F32X2(acc[0][j], acc[1][j], acc01[j]);
        UNPACK_F32X2(acc[2][j], acc[3][j], acc23[j]);
    }
    #pragma unroll
    for (int r = 0; r < 4; r++)
        #pragma unroll
        for (int j = 0; j < 16; j++) {
            float v = acc[r][j];
            v += __shfl_xor_sync(0xffffffffu, v, 16);
            v += __shfl_xor_sync(0xffffffffu, v, 8);
            v += __shfl_xor_sync(0xffffffffu, v, 4);
            v += __shfl_xor_sync(0xffffffffu, v, 2);
            v += __shfl_xor_sync(0xffffffffu, v, 1);
            acc[r][j] = v;
        }
    if (lane < 16) {
        #pragma unroll
        for (int r = 0; r < 4; r++) {
            int row = row0 + r;
            float o = 0.f;
            #pragma unroll
            for (int j = 0; j < 16; j++)
                if (lane == j) o = acc[r][j];
            g_hs[row * FH + lane] = o * g_dinv[row];
        }
    }
}

// Layer-1 gather, vectorized: lane = {vec = lane&3, slot = lane>>2}.
// Guard-free full iterations + one guarded remainder.
__global__ void k_gather1(const float* __restrict__ b1) {
    int warp = (blockIdx.x * blockDim.x + threadIdx.x) >> 5;
    int lane = threadIdx.x & 31;
    if (warp >= NN) return;
    int d = warp;
    int beg = g_rowptr[d], end = g_rowptr[d + 1];
    int vec = lane & 3, slot = lane >> 2;
    const float4* hv = (const float4*)g_hs;

    int nfull = beg + ((end - beg) & ~7);
    float4 acc = make_float4(0.f, 0.f, 0.f, 0.f);
    int base = beg;
    for (; base < nfull; base += 8) {
        int s = g_csr[base + slot];
        float4 v = hv[s * 4 + vec];
        acc.x += v.x; acc.y += v.y; acc.z += v.z; acc.w += v.w;
    }
    if (base + slot < end) {
        int s = g_csr[base + slot];
        float4 v = hv[s * 4 + vec];
        acc.x += v.x; acc.y += v.y; acc.z += v.z; acc.w += v.w;
    }
    #pragma unroll
    for (int m = 4; m < 32; m <<= 1) {
        acc.x += __shfl_xor_sync(0xffffffffu, acc.x, m);
        acc.y += __shfl_xor_sync(0xffffffffu, acc.y, m);
        acc.z += __shfl_xor_sync(0xffffffffu, acc.z, m);
        acc.w += __shfl_xor_sync(0xffffffffu, acc.w, m);
    }
    if (lane < 4) {
        float di = g_dinv[d];
        float4 self = hv[d * 4 + lane];
        float4 b = ((const float4*)b1)[lane];
        float4 z;
        z.x = fmaxf(di * (acc.x + self.x) + b.x, 0.f) * di;
        z.y = fmaxf(di * (acc.y + self.y) + b.y, 0.f) * di;
        z.z = fmaxf(di * (acc.z + self.z) + b.z, 0.f) * di;
        z.w = fmaxf(di * (acc.w + self.w) + b.w, 0.f) * di;
        ((float4*)g_zs)[d * 4 + lane] = z;
    }
}

// Layer-2 gather + full epilogue:
// a2 = dinv*(sum zs + zs[self]);  q = G a2 (G symmetric -> conflict-free LDS);
// p = a2.u + c/2
__global__ void k_gather2() {
    __shared__ float Gs[FH * FH];
    __shared__ float us[FH];
    __shared__ float cs;
    int tid = threadIdx.x;
    if (tid < FH * FH) Gs[tid] = g_G[tid];
    if (tid < FH) us[tid] = g_u[tid];
    if (tid == 0) cs = g_c;
    __syncthreads();

    int warp = (blockIdx.x * blockDim.x + tid) >> 5;
    int lane = tid & 31;
    if (warp >= NN) return;
    int d = warp;
    int beg = g_rowptr[d], end = g_rowptr[d + 1];
    int vec = lane & 3, slot = lane >> 2;
    const float4* zv = (const float4*)g_zs;

    int nfull = beg + ((end - beg) & ~7);
    float4 acc = make_float4(0.f, 0.f, 0.f, 0.f);
    int base = beg;
    for (; base < nfull; base += 8) {
        int s = g_csr[base + slot];
        float4 v = zv[s * 4 + vec];
        acc.x += v.x; acc.y += v.y; acc.z += v.z; acc.w += v.w;
    }
    if (base + slot < end) {
        int s = g_csr[base + slot];
        float4 v = zv[s * 4 + vec];
        acc.x += v.x; acc.y += v.y; acc.z += v.z; acc.w += v.w;
    }
    #pragma unroll
    for (int m = 4; m < 32; m <<= 1) {
        acc.x += __shfl_xor_sync(0xffffffffu, acc.x, m);
        acc.y += __shfl_xor_sync(0xffffffffu, acc.y, m);
        acc.z += __shfl_xor_sync(0xffffffffu, acc.z, m);
        acc.w += __shfl_xor_sync(0xffffffffu, acc.w, m);
    }
    float di = g_dinv[d];
    float4 self = zv[d * 4 + vec];
    float4 a4;
    a4.x = di * (acc.x + self.x);
    a4.y = di * (acc.y + self.y);
    a4.z = di * (acc.z + self.z);
    a4.w = di * (acc.w + self.w);

    // distribute all 16 a values to every lane: a[f] from lane f>>2, comp f&3
    float comp[4] = {a4.x, a4.y, a4.z, a4.w};
    float ak[16];
    #pragma unroll
    for (int f = 0; f < 16; f++)
        ak[f] = __shfl_sync(0xffffffffu, comp[f & 3], f >> 2);

    int j = lane & 15;
    float q = 0.f;
    #pragma unroll
    for (int k = 0; k < FH; k++)
        q += Gs[k * FH + j] * ak[k];          // G symmetric: conflict-free LDS
    float p = 0.5f * cs;
    #pragma unroll
    for (int k = 0; k < FH; k++)
        p += ak[k] * us[k];

    if (lane < 4) ((float4*)g_a2)[d * 4 + lane] = a4;
    if (lane < 16) {
        g_q[d * FH + j] = q;
        if (lane == 0) g_p[d] = p;
    }
}

// logits[e] = q[s] . a2[d] + p[s] + p[d]
__global__ void k_logits(const int* __restrict__ pos, const int* __restrict__ neg,
                         float* __restrict__ out) {
    int e = blockIdx.x * blockDim.x + threadIdx.x;
    if (e >= 2 * ETEST) return;
    int s, d;
    if (e < ETEST) { s = pos[e];         d = pos[ETEST + e]; }
    else           { s = neg[e - ETEST]; d = neg[ETEST + (e - ETEST)]; }
    const float4* qs = (const float4*)(g_q  + (size_t)s * FH);
    const float4* ad = (const float4*)(g_a2 + (size_t)d * FH);
    float acc = g_p[s] + g_p[d];
    #pragma unroll
    for (int v = 0; v < 4; v++) {
        float4 qv = qs[v], av = ad[v];
        acc += qv.x * av.x + qv.y * av.y + qv.z * av.z + qv.w * av.w;
    }
    out[e] = acc;
}

// ---------------- launch ----------------
extern "C" void kernel_launch(void* const* d_in, const int* in_sizes, int n_in,
                              void* d_out, int out_size) {
    // Resolve inputs BY SIZE (robust to metadata ordering).
    const float* x  = nullptr; const int* tei = nullptr;
    const int*   pos = nullptr; const int* neg = nullptr;
    const float* W1 = nullptr; const float* b1 = nullptr;
    const float* W2 = nullptr; const float* b2 = nullptr;
    for (int i = 0; i < n_in; i++) {
        int sz = in_sizes[i];
        const void* p = d_in[i];
        if      (sz == NN * FIN)   x   = (const float*)p;
        else if (sz == 2 * EE)     tei = (const int*)p;
        else if (sz == 2 * ETEST) { if (!pos) pos = (const int*)p; else neg = (const int*)p; }
        else if (sz == FIN * FH)   W1  = (const float*)p;
        else if (sz == FH)         b1  = (const float*)p;
        else if (sz == FH * FOUT)  W2  = (const float*)p;
        else if (sz == FOUT)       b2  = (const float*)p;
    }
    float* out = (float*)d_out;

    const int* src = tei;
    const int* dst = tei + EE;

    k_deginit<<<1 + EE / 4 / 256, 256>>>(dst, W2, b2);    // 1: deg + G/u/c
    k_scan1  <<<NB, 512>>>();                              // 2
    k_scan3  <<<(NN + 255) / 256, 256>>>();                // 3: offsets+dinv+cursor
    k_fill   <<<EE / 4 / 256, 256>>>(src, dst);            // 4  (profiled slot)
    k_gemm1  <<<(NN / 4 + 7) / 8, 256>>>(x, W1);           // 5
    k_gather1<<<(NN * 32 + 255) / 256, 256>>>(b1);         // 6
    k_gather2<<<(NN * 32 + 255) / 256, 256>>>();           // 7
    k_logits <<<(2 * ETEST + 255) / 256, 256>>>(pos, neg, out);  // 8
}

// round 15
// speedup vs baseline: 2.8706x; 1.0601x over previous
#include <cuda_runtime.h>
#include <cuda_bf16.h>
#include <cstdint>

// Problem constants (fixed by the reference setup)
#define NN     100000
#define EE     3200000
#define ETEST  500000
#define FIN    256
#define FH     16
#define FOUT   64
#define NB     196        // scan blocks: ceil(NN/512)

// packed dual-FMA (Blackwell f32x2 pipe; 2 FMAs per issue)
#define FMA_F32X2(d, a, b, c) \
    asm("fma.rn.f32x2 %0, %1, %2, %3;" : "=l"(d) : "l"(a), "l"(b), "l"(c))
#define PACK_F32X2(out, lo, hi) \
    asm("mov.b64 %0, {%1, %2};" : "=l"(out) : "f"(lo), "f"(hi))
#define UNPACK_F32X2(lo, hi, in) \
    asm("mov.b64 {%0, %1}, %2;" : "=f"(lo), "=f"(hi) : "l"(in))

// ---------------- device scratch (no allocs allowed) ----------------
// Static zero-init covers the first run; scan3 re-initializes cursor/deg
// every execution, so graph replays see identical starting state.
__device__ __align__(256) int   g_deg   [NN];
__device__ __align__(256) int   g_cursor[NN];     // absolute write cursors (= rowptr at fill start)
__device__ __align__(256) int   g_rowptr[NN + 1];
__device__ __align__(256) int   g_bsum  [NB];
__device__ __align__(256) int   g_csr   [EE];
__device__ __align__(256) float g_dinv[NN];
__device__ __align__(256) float g_hs [NN * FH];   // (x@W1) * dinv[row]
__device__ __align__(256) float g_zs [NN * FH];   // relu(z1) * dinv[row]
__device__ __align__(256) float g_a2 [NN * FH];   // layer-2 node features (16-dim)
__device__ __align__(256) float g_q  [NN * FH];   // q = G @ a2
__device__ __align__(256) float g_p  [NN];        // p = a2 . u + c/2
__device__ __align__(256) float g_G  [FH * FH];   // W2 W2^T (symmetric)
__device__ __align__(256) float g_u  [FH];        // W2 b2
__device__ float g_c;                             // ||b2||^2

// ---------------- kernels ----------------

// block 0: G/u/c precompute.  blocks 1..: in-degree over dst, 4 edges/thread.
__global__ void k_deginit(const int* __restrict__ dst,
                          const float* __restrict__ W2,
                          const float* __restrict__ b2) {
    if (blockIdx.x == 0) {
        int t = threadIdx.x;
        if (t < FH * FH) {
            int i = t >> 4, j = t & 15;
            float s = 0.f;
            #pragma unroll
            for (int k = 0; k < FOUT; k++) s += W2[i * FOUT + k] * W2[j * FOUT + k];
            g_G[t] = s;
            if (t < FH) {
                float su = 0.f;
                #pragma unroll
                for (int k = 0; k < FOUT; k++) su += W2[t * FOUT + k] * b2[k];
                g_u[t] = su;
            }
            if (t == 0) {
                float sc = 0.f;
                #pragma unroll
                for (int k = 0; k < FOUT; k++) sc += b2[k] * b2[k];
                g_c = sc;
            }
        }
    } else {
        int e = ((blockIdx.x - 1) * blockDim.x + threadIdx.x) * 4;
        if (e >= EE) return;
        int4 d4 = *(const int4*)(dst + e);
        atomicAdd(&g_deg[d4.x], 1);
        atomicAdd(&g_deg[d4.y], 1);
        atomicAdd(&g_deg[d4.z], 1);
        atomicAdd(&g_deg[d4.w], 1);
    }
}

// block-local exclusive prefix scan of g_deg into g_rowptr, block sums to g_bsum
__global__ void k_scan1() {
    __shared__ int sh[512];
    int tid = threadIdx.x;
    int i = blockIdx.x * 512 + tid;
    int v = (i < NN) ? g_deg[i] : 0;
    sh[tid] = v;
    __syncthreads();
    #pragma unroll
    for (int off = 1; off < 512; off <<= 1) {
        int t = (tid >= off) ? sh[tid - off] : 0;
        __syncthreads();
        sh[tid] += t;
        __syncthreads();
    }
    if (i < NN) g_rowptr[i] = sh[tid] - v;       // exclusive within block
    if (tid == 511) g_bsum[blockIdx.x] = sh[511];
}

// Every block redundantly scans the 196 block sums (inclusive) in smem, then
// adds its group's exclusive offset to rowptr.  Also: dinv, cursor := rowptr
// (absolute fill cursors), deg reset for next replay, rowptr[NN].
__global__ void k_scan3() {
    __shared__ int sh[256];
    int tid = threadIdx.x;
    int v = (tid < NB) ? g_bsum[tid] : 0;
    sh[tid] = v;
    __syncthreads();
    #pragma unroll
    for (int off = 1; off < 256; off <<= 1) {
        int t = (tid >= off) ? sh[tid - off] : 0;
        __syncthreads();
        sh[tid] += t;
        __syncthreads();
    }
    int g = blockIdx.x >> 1;                     // 512-group of this block
    int S = (g == 0) ? 0 : sh[g - 1];            // exclusive offset (broadcast)
    int i = blockIdx.x * 256 + tid;
    if (i < NN) {
        int rp = g_rowptr[i] + S;
        g_rowptr[i] = rp;
        g_cursor[i] = rp;                        // absolute cursor for k_fill part
        g_dinv[i] = rsqrtf((float)g_deg[i] + 1.0f);
        g_deg[i] = 0;                            // self-clean for next replay
    }
    if (i == 0) g_rowptr[NN] = EE;
}

// FUSED fill + gemm1.  Both depend only on scan3; fill is LTS/atomic-bound
// (issue 1.8%), gemm1 is FMA/DRAM-bound -> co-schedule on the same SMs.
// Odd blocks: CSR fill slice (1024 edges).  Even blocks: gemm slice (32 rows).
__global__ void k_fillgemm(const int* __restrict__ src, const int* __restrict__ dst,
                           const float* __restrict__ x, const float* __restrict__ W1) {
    if (blockIdx.x & 1) {
        // ---- fill: pos = atomicAdd(cursor[d]); csr[pos] = src ----
        int fb = blockIdx.x >> 1;                // 0..3124
        int e = (fb * 256 + threadIdx.x) * 4;    // 3125*256*4 == EE exactly
        int4 s4 = *(const int4*)(src + e);
        int4 d4 = *(const int4*)(dst + e);
        int p0 = atomicAdd(&g_cursor[d4.x], 1);
        g_csr[p0] = s4.x;
        int p1 = atomicAdd(&g_cursor[d4.y], 1);
        g_csr[p1] = s4.y;
        int p2 = atomicAdd(&g_cursor[d4.z], 1);
        g_csr[p2] = s4.z;
        int p3 = atomicAdd(&g_cursor[d4.w], 1);
        g_csr[p3] = s4.w;
        return;
    }
    // ---- gemm1: hs = (x @ W1) * dinv[row], 4 rows/warp, f32x2 FMAs ----
    __shared__ float w[FIN * 17];
    int gb = blockIdx.x >> 1;                    // 0..3124
    int tid = threadIdx.x;
    for (int i = tid; i < FIN * FH; i += blockDim.x) {
        int k = i >> 4, j = i & 15;
        w[k * 17 + j] = W1[i];
    }
    __syncthreads();

    int warp = tid >> 5, lane = tid & 31;
    int row0 = (gb * 8 + warp) * 4;              // 3125*8*4 == NN exactly

    unsigned long long acc01[16], acc23[16];
    #pragma unroll
    for (int j = 0; j < 16; j++) { acc01[j] = 0ull; acc23[j] = 0ull; }

    const float* x0 = x + (size_t)row0 * FIN;
    #pragma unroll
    for (int t = 0; t < 8; t++) {
        int k = lane + 32 * t;
        float xv0 = x0[k];
        float xv1 = x0[FIN + k];
        float xv2 = x0[2 * FIN + k];
        float xv3 = x0[3 * FIN + k];
        unsigned long long x01, x23;
        PACK_F32X2(x01, xv0, xv1);
        PACK_F32X2(x23, xv2, xv3);
        #pragma unroll
        for (int j = 0; j < 16; j++) {
            float wv = w[k * 17 + j];
            unsigned long long w2;
            PACK_F32X2(w2, wv, wv);
            FMA_F32X2(acc01[j], x01, w2, acc01[j]);
            FMA_F32X2(acc23[j], x23, w2, acc23[j]);
        }
    }
    float acc[4][16];
    #pragma unroll
    for (int j = 0; j < 16; j++) {
        UNPACK_F32X2(acc[0][j], acc[1][j], acc01[j]);
        UNPACK_F32X2(acc[2][j], acc[3][j], acc23[j]);
    }
    #pragma unroll
    for (int r = 0; r < 4; r++)
        #pragma unroll
        for (int j = 0; j < 16; j++) {
            float v = acc[r][j];
            v += __shfl_xor_sync(0xffffffffu, v, 16);
            v += __shfl_xor_sync(0xffffffffu, v, 8);
            v += __shfl_xor_sync(0xffffffffu, v, 4);
            v += __shfl_xor_sync(0xffffffffu, v, 2);
            v += __shfl_xor_sync(0xffffffffu, v, 1);
            acc[r][j] = v;
        }
    if (lane < 16) {
        #pragma unroll
        for (int r = 0; r < 4; r++) {
            int row = row0 + r;
            float o = 0.f;
            #pragma unroll
            for (int j = 0; j < 16; j++)
                if (lane == j) o = acc[r][j];
            g_hs[row * FH + lane] = o * g_dinv[row];
        }
    }
}

// Layer-1 gather, vectorized: lane = {vec = lane&3, slot = lane>>2}.
// unroll 4: batches 4 independent idx+row chains (degree~32 = 4 iterations).
__global__ void k_gather1(const float* __restrict__ b1) {
    int warp = (blockIdx.x * blockDim.x + threadIdx.x) >> 5;
    int lane = threadIdx.x & 31;
    if (warp >= NN) return;
    int d = warp;
    int beg = g_rowptr[d], end = g_rowptr[d + 1];
    int vec = lane & 3, slot = lane >> 2;
    const float4* hv = (const float4*)g_hs;

    int nfull = beg + ((end - beg) & ~7);
    float4 acc = make_float4(0.f, 0.f, 0.f, 0.f);
    int base = beg;
    #pragma unroll 4
    for (; base < nfull; base += 8) {
        int s = g_csr[base + slot];
        float4 v = hv[s * 4 + vec];
        acc.x += v.x; acc.y += v.y; acc.z += v.z; acc.w += v.w;
    }
    if (base + slot < end) {
        int s = g_csr[base + slot];
        float4 v = hv[s * 4 + vec];
        acc.x += v.x; acc.y += v.y; acc.z += v.z; acc.w += v.w;
    }
    #pragma unroll
    for (int m = 4; m < 32; m <<= 1) {
        acc.x += __shfl_xor_sync(0xffffffffu, acc.x, m);
        acc.y += __shfl_xor_sync(0xffffffffu, acc.y, m);
        acc.z += __shfl_xor_sync(0xffffffffu, acc.z, m);
        acc.w += __shfl_xor_sync(0xffffffffu, acc.w, m);
    }
    if (lane < 4) {
        float di = g_dinv[d];
        float4 self = hv[d * 4 + lane];
        float4 b = ((const float4*)b1)[lane];
        float4 z;
        z.x = fmaxf(di * (acc.x + self.x) + b.x, 0.f) * di;
        z.y = fmaxf(di * (acc.y + self.y) + b.y, 0.f) * di;
        z.z = fmaxf(di * (acc.z + self.z) + b.z, 0.f) * di;
        z.w = fmaxf(di * (acc.w + self.w) + b.w, 0.f) * di;
        ((float4*)g_zs)[d * 4 + lane] = z;
    }
}

// Layer-2 gather + full epilogue:
// a2 = dinv*(sum zs + zs[self]);  q = G a2 (G symmetric -> conflict-free LDS);
// p = a2.u + c/2
__global__ void k_gather2() {
    __shared__ float Gs[FH * FH];
    __shared__ float us[FH];
    __shared__ float cs;
    int tid = threadIdx.x;
    if (tid < FH * FH) Gs[tid] = g_G[tid];
    if (tid < FH) us[tid] = g_u[tid];
    if (tid == 0) cs = g_c;
    __syncthreads();

    int warp = (blockIdx.x * blockDim.x + tid) >> 5;
    int lane = tid & 31;
    if (warp >= NN) return;
    int d = warp;
    int beg = g_rowptr[d], end = g_rowptr[d + 1];
    int vec = lane & 3, slot = lane >> 2;
    const float4* zv = (const float4*)g_zs;

    int nfull = beg + ((end - beg) & ~7);
    float4 acc = make_float4(0.f, 0.f, 0.f, 0.f);
    int base = beg;
    #pragma unroll 4
    for (; base < nfull; base += 8) {
        int s = g_csr[base + slot];
        float4 v = zv[s * 4 + vec];
        acc.x += v.x; acc.y += v.y; acc.z += v.z; acc.w += v.w;
    }
    if (base + slot < end) {
        int s = g_csr[base + slot];
        float4 v = zv[s * 4 + vec];
        acc.x += v.x; acc.y += v.y; acc.z += v.z; acc.w += v.w;
    }
    #pragma unroll
    for (int m = 4; m < 32; m <<= 1) {
        acc.x += __shfl_xor_sync(0xffffffffu, acc.x, m);
        acc.y += __shfl_xor_sync(0xffffffffu, acc.y, m);
        acc.z += __shfl_xor_sync(0xffffffffu, acc.z, m);
        acc.w += __shfl_xor_sync(0xffffffffu, acc.w, m);
    }
    float di = g_dinv[d];
    float4 self = zv[d * 4 + vec];
    float4 a4;
    a4.x = di * (acc.x + self.x);
    a4.y = di * (acc.y + self.y);
    a4.z = di * (acc.z + self.z);
    a4.w = di * (acc.w + self.w);

    // distribute all 16 a values to every lane: a[f] from lane f>>2, comp f&3
    float comp[4] = {a4.x, a4.y, a4.z, a4.w};
    float ak[16];
    #pragma unroll
    for (int f = 0; f < 16; f++)
        ak[f] = __shfl_sync(0xffffffffu, comp[f & 3], f >> 2);

    int j = lane & 15;
    float q = 0.f;
    #pragma unroll
    for (int k = 0; k < FH; k++)
        q += Gs[k * FH + j] * ak[k];          // G symmetric: conflict-free LDS
    float p = 0.5f * cs;
    #pragma unroll
    for (int k = 0; k < FH; k++)
        p += ak[k] * us[k];

    if (lane < 4) ((float4*)g_a2)[d * 4 + lane] = a4;
    if (lane < 16) {
        g_q[d * FH + j] = q;
        if (lane == 0) g_p[d] = p;
    }
}

// logits[e] = q[s] . a2[d] + p[s] + p[d]
__global__ void k_logits(const int* __restrict__ pos, const int* __restrict__ neg,
                         float* __restrict__ out) {
    int e = blockIdx.x * blockDim.x + threadIdx.x;
    if (e >= 2 * ETEST) return;
    int s, d;
    if (e < ETEST) { s = pos[e];         d = pos[ETEST + e]; }
    else           { s = neg[e - ETEST]; d = neg[ETEST + (e - ETEST)]; }
    const float4* qs = (const float4*)(g_q  + (size_t)s * FH);
    const float4* ad = (const float4*)(g_a2 + (size_t)d * FH);
    float acc = g_p[s] + g_p[d];
    #pragma unroll
    for (int v = 0; v < 4; v++) {
        float4 qv = qs[v], av = ad[v];
        acc += qv.x * av.x + qv.y * av.y + qv.z * av.z + qv.w * av.w;
    }
    out[e] = acc;
}

// ---------------- launch ----------------
extern "C" void kernel_launch(void* const* d_in, const int* in_sizes, int n_in,
                              void* d_out, int out_size) {
    // Resolve inputs BY SIZE (robust to metadata ordering).
    const float* x  = nullptr; const int* tei = nullptr;
    const int*   pos = nullptr; const int* neg = nullptr;
    const float* W1 = nullptr; const float* b1 = nullptr;
    const float* W2 = nullptr; const float* b2 = nullptr;
    for (int i = 0; i < n_in; i++) {
        int sz = in_sizes[i];
        const void* p = d_in[i];
        if      (sz == NN * FIN)   x   = (const float*)p;
        else if (sz == 2 * EE)     tei = (const int*)p;
        else if (sz == 2 * ETEST) { if (!pos) pos = (const int*)p; else neg = (const int*)p; }
        else if (sz == FIN * FH)   W1  = (const float*)p;
        else if (sz == FH)         b1  = (const float*)p;
        else if (sz == FH * FOUT)  W2  = (const float*)p;
        else if (sz == FOUT)       b2  = (const float*)p;
    }
    float* out = (float*)d_out;

    const int* src = tei;
    const int* dst = tei + EE;

    k_deginit <<<1 + EE / 4 / 256, 256>>>(dst, W2, b2);     // 1: deg + G/u/c
    k_scan1   <<<NB, 512>>>();                               // 2
    k_scan3   <<<(NN + 255) / 256, 256>>>();                 // 3: offsets+dinv+cursor
    k_fillgemm<<<6250, 256>>>(src, dst, x, W1);              // 4: fill || gemm1 (profiled)
    k_gather1 <<<(NN * 32 + 255) / 256, 256>>>(b1);          // 5
    k_gather2 <<<(NN * 32 + 255) / 256, 256>>>();            // 6
    k_logits  <<<(2 * ETEST + 255) / 256, 256>>>(pos, neg, out);  // 7
}

// round 17
// speedup vs baseline: 2.9815x; 1.0386x over previous
#include <cuda_runtime.h>
#include <cuda_bf16.h>
#include <cstdint>

// Problem constants (fixed by the reference setup)
#define NN     100000
#define EE     3200000
#define ETEST  500000
#define FIN    256
#define FH     16
#define FOUT   64
#define NB     196        // scan blocks: ceil(NN/512)

// packed dual-FMA (Blackwell f32x2 pipe; 2 FMAs per issue)
#define FMA_F32X2(d, a, b, c) \
    asm("fma.rn.f32x2 %0, %1, %2, %3;" : "=l"(d) : "l"(a), "l"(b), "l"(c))
#define PACK_F32X2(out, lo, hi) \
    asm("mov.b64 %0, {%1, %2};" : "=l"(out) : "f"(lo), "f"(hi))
#define UNPACK_F32X2(lo, hi, in) \
    asm("mov.b64 {%0, %1}, %2;" : "=f"(lo), "=f"(hi) : "l"(in))

// ---------------- device scratch (no allocs allowed) ----------------
// Static zero-init covers the first run; scan3 re-initializes cursor/deg
// every execution, so graph replays see identical starting state.
__device__ __align__(256) int   g_deg   [NN];
__device__ __align__(256) int   g_cursor[NN];     // absolute write cursors (= rowptr at fill start)
__device__ __align__(256) int   g_rowptr[NN + 1];
__device__ __align__(256) int   g_bsum  [NB];
__device__ __align__(256) int   g_csr   [EE];
__device__ __align__(256) float g_dinv[NN];
__device__ __align__(256) float g_hs [NN * FH];   // (x@W1) * dinv[row]
__device__ __align__(256) float g_zs [NN * FH];   // relu(z1) * dinv[row]
__device__ __align__(256) float g_a2 [NN * FH];   // layer-2 node features (16-dim)
__device__ __align__(256) float g_q  [NN * FH];   // q = G @ a2
__device__ __align__(256) float g_p  [NN];        // p = a2 . u + c/2
__device__ __align__(256) float g_G  [FH * FH];   // W2 W2^T (symmetric)
__device__ __align__(256) float g_u  [FH];        // W2 b2
__device__ float g_c;                             // ||b2||^2

// ---------------- kernels ----------------

// block 0: G/u/c precompute.  blocks 1..: in-degree over dst, 4 edges/thread.
__global__ void k_deginit(const int* __restrict__ dst,
                          const float* __restrict__ W2,
                          const float* __restrict__ b2) {
    if (blockIdx.x == 0) {
        int t = threadIdx.x;
        if (t < FH * FH) {
            int i = t >> 4, j = t & 15;
            float s = 0.f;
            #pragma unroll
            for (int k = 0; k < FOUT; k++) s += W2[i * FOUT + k] * W2[j * FOUT + k];
            g_G[t] = s;
            if (t < FH) {
                float su = 0.f;
                #pragma unroll
                for (int k = 0; k < FOUT; k++) su += W2[t * FOUT + k] * b2[k];
                g_u[t] = su;
            }
            if (t == 0) {
                float sc = 0.f;
                #pragma unroll
                for (int k = 0; k < FOUT; k++) sc += b2[k] * b2[k];
                g_c = sc;
            }
        }
    } else {
        int e = ((blockIdx.x - 1) * blockDim.x + threadIdx.x) * 4;
        if (e >= EE) return;
        int4 d4 = *(const int4*)(dst + e);
        atomicAdd(&g_deg[d4.x], 1);
        atomicAdd(&g_deg[d4.y], 1);
        atomicAdd(&g_deg[d4.z], 1);
        atomicAdd(&g_deg[d4.w], 1);
    }
}

// block-local exclusive prefix scan of g_deg into g_rowptr, block sums to g_bsum
__global__ void k_scan1() {
    __shared__ int sh[512];
    int tid = threadIdx.x;
    int i = blockIdx.x * 512 + tid;
    int v = (i < NN) ? g_deg[i] : 0;
    sh[tid] = v;
    __syncthreads();
    #pragma unroll
    for (int off = 1; off < 512; off <<= 1) {
        int t = (tid >= off) ? sh[tid - off] : 0;
        __syncthreads();
        sh[tid] += t;
        __syncthreads();
    }
    if (i < NN) g_rowptr[i] = sh[tid] - v;       // exclusive within block
    if (tid == 511) g_bsum[blockIdx.x] = sh[511];
}

// Every block redundantly scans the 196 block sums (inclusive) in smem, then
// adds its group's exclusive offset to rowptr.  Also: dinv, cursor := rowptr
// (absolute fill cursors), deg reset for next replay, rowptr[NN].
__global__ void k_scan3() {
    __shared__ int sh[256];
    int tid = threadIdx.x;
    int v = (tid < NB) ? g_bsum[tid] : 0;
    sh[tid] = v;
    __syncthreads();
    #pragma unroll
    for (int off = 1; off < 256; off <<= 1) {
        int t = (tid >= off) ? sh[tid - off] : 0;
        __syncthreads();
        sh[tid] += t;
        __syncthreads();
    }
    int g = blockIdx.x >> 1;                     // 512-group of this block
    int S = (g == 0) ? 0 : sh[g - 1];            // exclusive offset (broadcast)
    int i = blockIdx.x * 256 + tid;
    if (i < NN) {
        int rp = g_rowptr[i] + S;
        g_rowptr[i] = rp;
        g_cursor[i] = rp;                        // absolute cursor for fill part
        g_dinv[i] = rsqrtf((float)g_deg[i] + 1.0f);
        g_deg[i] = 0;                            // self-clean for next replay
    }
    if (i == 0) g_rowptr[NN] = EE;
}

// FUSED fill + gemm1, occupancy-tuned (>=4 blocks/SM).
// Grid 9375: b%3==2 -> fill slice (1024 edges, 3125 blocks);
//            else   -> gemm slice (16 rows, 6250 blocks, 2 rows/warp).
__global__ void __launch_bounds__(256, 4)
k_fillgemm(const int* __restrict__ src, const int* __restrict__ dst,
           const float* __restrict__ x, const float* __restrict__ W1) {
    int b = blockIdx.x;
    int r3 = b % 3, q3 = b / 3;
    if (r3 == 2) {
        // ---- fill: pos = atomicAdd(cursor[d]); csr[pos] = src ----
        int e = (q3 * 256 + threadIdx.x) * 4;    // 3125*256*4 == EE exactly
        int4 s4 = *(const int4*)(src + e);
        int4 d4 = *(const int4*)(dst + e);
        int p0 = atomicAdd(&g_cursor[d4.x], 1);
        g_csr[p0] = s4.x;
        int p1 = atomicAdd(&g_cursor[d4.y], 1);
        g_csr[p1] = s4.y;
        int p2 = atomicAdd(&g_cursor[d4.z], 1);
        g_csr[p2] = s4.z;
        int p3 = atomicAdd(&g_cursor[d4.w], 1);
        g_csr[p3] = s4.w;
        return;
    }
    // ---- gemm1: hs = (x @ W1) * dinv[row], 2 rows/warp, f32x2 FMAs ----
    __shared__ float w[FIN * 17];
    int gb = 2 * q3 + r3;                        // 0..6249
    int tid = threadIdx.x;
    for (int i = tid; i < FIN * FH; i += blockDim.x) {
        int k = i >> 4, j = i & 15;
        w[k * 17 + j] = W1[i];
    }
    __syncthreads();

    int warp = tid >> 5, lane = tid & 31;
    int row0 = (gb * 8 + warp) * 2;              // 6250*8*2 == NN exactly

    unsigned long long acc01[16];
    #pragma unroll
    for (int j = 0; j < 16; j++) acc01[j] = 0ull;

    const float* x0 = x + (size_t)row0 * FIN;
    #pragma unroll
    for (int t = 0; t < 8; t++) {
        int k = lane + 32 * t;
        float xv0 = x0[k];
        float xv1 = x0[FIN + k];
        unsigned long long x01;
        PACK_F32X2(x01, xv0, xv1);
        #pragma unroll
        for (int j = 0; j < 16; j++) {
            float wv = w[k * 17 + j];
            unsigned long long w2;
            PACK_F32X2(w2, wv, wv);
            FMA_F32X2(acc01[j], x01, w2, acc01[j]);
        }
    }
    // unpack and butterfly-reduce each output across the warp
    float acc[2][16];
    #pragma unroll
    for (int j = 0; j < 16; j++)
        UNPACK_F32X2(acc[0][j], acc[1][j], acc01[j]);
    #pragma unroll
    for (int r = 0; r < 2; r++)
        #pragma unroll
        for (int j = 0; j < 16; j++) {
            float v = acc[r][j];
            v += __shfl_xor_sync(0xffffffffu, v, 16);
            v += __shfl_xor_sync(0xffffffffu, v, 8);
            v += __shfl_xor_sync(0xffffffffu, v, 4);
            v += __shfl_xor_sync(0xffffffffu, v, 2);
            v += __shfl_xor_sync(0xffffffffu, v, 1);
            acc[r][j] = v;
        }
    if (lane < 16) {
        #pragma unroll
        for (int r = 0; r < 2; r++) {
            int row = row0 + r;
            float o = 0.f;
            #pragma unroll
            for (int j = 0; j < 16; j++)
                if (lane == j) o = acc[r][j];
            g_hs[row * FH + lane] = o * g_dinv[row];
        }
    }
}

// Layer-1 gather, vectorized: lane = {vec = lane&3, slot = lane>>2}.
// unroll 4: batches 4 independent idx+row chains (degree~32 = 4 iterations).
__global__ void k_gather1(const float* __restrict__ b1) {
    int warp = (blockIdx.x * blockDim.x + threadIdx.x) >> 5;
    int lane = threadIdx.x & 31;
    if (warp >= NN) return;
    int d = warp;
    int beg = g_rowptr[d], end = g_rowptr[d + 1];
    int vec = lane & 3, slot = lane >> 2;
    const float4* hv = (const float4*)g_hs;

    int nfull = beg + ((end - beg) & ~7);
    float4 acc = make_float4(0.f, 0.f, 0.f, 0.f);
    int base = beg;
    #pragma unroll 4
    for (; base < nfull; base += 8) {
        int s = g_csr[base + slot];
        float4 v = hv[s * 4 + vec];
        acc.x += v.x; acc.y += v.y; acc.z += v.z; acc.w += v.w;
    }
    if (base + slot < end) {
        int s = g_csr[base + slot];
        float4 v = hv[s * 4 + vec];
        acc.x += v.x; acc.y += v.y; acc.z += v.z; acc.w += v.w;
    }
    #pragma unroll
    for (int m = 4; m < 32; m <<= 1) {
        acc.x += __shfl_xor_sync(0xffffffffu, acc.x, m);
        acc.y += __shfl_xor_sync(0xffffffffu, acc.y, m);
        acc.z += __shfl_xor_sync(0xffffffffu, acc.z, m);
        acc.w += __shfl_xor_sync(0xffffffffu, acc.w, m);
    }
    if (lane < 4) {
        float di = g_dinv[d];
        float4 self = hv[d * 4 + lane];
        float4 b = ((const float4*)b1)[lane];
        float4 z;
        z.x = fmaxf(di * (acc.x + self.x) + b.x, 0.f) * di;
        z.y = fmaxf(di * (acc.y + self.y) + b.y, 0.f) * di;
        z.z = fmaxf(di * (acc.z + self.z) + b.z, 0.f) * di;
        z.w = fmaxf(di * (acc.w + self.w) + b.w, 0.f) * di;
        ((float4*)g_zs)[d * 4 + lane] = z;
    }
}

// Layer-2 gather + full epilogue:
// a2 = dinv*(sum zs + zs[self]);  q = G a2 (G symmetric -> conflict-free LDS);
// p = a2.u + c/2
__global__ void k_gather2() {
    __shared__ float Gs[FH * FH];
    __shared__ float us[FH];
    __shared__ float cs;
    int tid = threadIdx.x;
    if (tid < FH * FH) Gs[tid] = g_G[tid];
    if (tid < FH) us[tid] = g_u[tid];
    if (tid == 0) cs = g_c;
    __syncthreads();

    int warp = (blockIdx.x * blockDim.x + tid) >> 5;
    int lane = tid & 31;
    if (warp >= NN) return;
    int d = warp;
    int beg = g_rowptr[d], end = g_rowptr[d + 1];
    int vec = lane & 3, slot = lane >> 2;
    const float4* zv = (const float4*)g_zs;

    int nfull = beg + ((end - beg) & ~7);
    float4 acc = make_float4(0.f, 0.f, 0.f, 0.f);
    int base = beg;
    #pragma unroll 4
    for (; base < nfull; base += 8) {
        int s = g_csr[base + slot];
        float4 v = zv[s * 4 + vec];
        acc.x += v.x; acc.y += v.y; acc.z += v.z; acc.w += v.w;
    }
    if (base + slot < end) {
        int s = g_csr[base + slot];
        float4 v = zv[s * 4 + vec];
        acc.x += v.x; acc.y += v.y; acc.z += v.z; acc.w += v.w;
    }
    #pragma unroll
    for (int m = 4; m < 32; m <<= 1) {
        acc.x += __shfl_xor_sync(0xffffffffu, acc.x, m);
        acc.y += __shfl_xor_sync(0xffffffffu, acc.y, m);
        acc.z += __shfl_xor_sync(0xffffffffu, acc.z, m);
        acc.w += __shfl_xor_sync(0xffffffffu, acc.w, m);
    }
    float di = g_dinv[d];
    float4 self = zv[d * 4 + vec];
    float4 a4;
    a4.x = di * (acc.x + self.x);
    a4.y = di * (acc.y + self.y);
    a4.z = di * (acc.z + self.z);
    a4.w = di * (acc.w + self.w);

    // distribute all 16 a values to every lane: a[f] from lane f>>2, comp f&3
    float comp[4] = {a4.x, a4.y, a4.z, a4.w};
    float ak[16];
    #pragma unroll
    for (int f = 0; f < 16; f++)
        ak[f] = __shfl_sync(0xffffffffu, comp[f & 3], f >> 2);

    int j = lane & 15;
    float q = 0.f;
    #pragma unroll
    for (int k = 0; k < FH; k++)
        q += Gs[k * FH + j] * ak[k];          // G symmetric: conflict-free LDS
    float p = 0.5f * cs;
    #pragma unroll
    for (int k = 0; k < FH; k++)
        p += ak[k] * us[k];

    if (lane < 4) ((float4*)g_a2)[d * 4 + lane] = a4;
    if (lane < 16) {
        g_q[d * FH + j] = q;
        if (lane == 0) g_p[d] = p;
    }
}

// logits[e] = q[s] . a2[d] + p[s] + p[d]
__global__ void k_logits(const int* __restrict__ pos, const int* __restrict__ neg,
                         float* __restrict__ out) {
    int e = blockIdx.x * blockDim.x + threadIdx.x;
    if (e >= 2 * ETEST) return;
    int s, d;
    if (e < ETEST) { s = pos[e];         d = pos[ETEST + e]; }
    else           { s = neg[e - ETEST]; d = neg[ETEST + (e - ETEST)]; }
    const float4* qs = (const float4*)(g_q  + (size_t)s * FH);
    const float4* ad = (const float4*)(g_a2 + (size_t)d * FH);
    float acc = g_p[s] + g_p[d];
    #pragma unroll
    for (int v = 0; v < 4; v++) {
        float4 qv = qs[v], av = ad[v];
        acc += qv.x * av.x + qv.y * av.y + qv.z * av.z + qv.w * av.w;
    }
    out[e] = acc;
}

// ---------------- launch ----------------
extern "C" void kernel_launch(void* const* d_in, const int* in_sizes, int n_in,
                              void* d_out, int out_size) {
    // Resolve inputs BY SIZE (robust to metadata ordering).
    const float* x  = nullptr; const int* tei = nullptr;
    const int*   pos = nullptr; const int* neg = nullptr;
    const float* W1 = nullptr; const float* b1 = nullptr;
    const float* W2 = nullptr; const float* b2 = nullptr;
    for (int i = 0; i < n_in; i++) {
        int sz = in_sizes[i];
        const void* p = d_in[i];
        if      (sz == NN * FIN)   x   = (const float*)p;
        else if (sz == 2 * EE)     tei = (const int*)p;
        else if (sz == 2 * ETEST) { if (!pos) pos = (const int*)p; else neg = (const int*)p; }
        else if (sz == FIN * FH)   W1  = (const float*)p;
        else if (sz == FH)         b1  = (const float*)p;
        else if (sz == FH * FOUT)  W2  = (const float*)p;
        else if (sz == FOUT)       b2  = (const float*)p;
    }
    float* out = (float*)d_out;

    const int* src = tei;
    const int* dst = tei + EE;

    k_deginit <<<1 + EE / 4 / 256, 256>>>(dst, W2, b2);     // 1: deg + G/u/c
    k_scan1   <<<NB, 512>>>();                               // 2
    k_scan3   <<<(NN + 255) / 256, 256>>>();                 // 3: offsets+dinv+cursor
    k_fillgemm<<<9375, 256>>>(src, dst, x, W1);              // 4: fill || gemm1 (profiled)
    k_gather1 <<<(NN * 32 + 255) / 256, 256>>>(b1);          // 5
    k_gather2 <<<(NN * 32 + 255) / 256, 256>>>();            // 6
    k_logits  <<<(2 * ETEST + 255) / 256, 256>>>(pos, neg, out);  // 7
}